// round 3
// baseline (speedup 1.0000x reference)
#include <cuda_runtime.h>
#include <math.h>

#define Bz 64
#define Tz 512
#define Dz 1024
#define Hz 1024
#define Gz 4096          // 4*H
#define EPSz 1e-5f
#define NCTA 128

typedef unsigned long long ull;

// ---------------- scratch (device globals; no runtime allocation) ----------------
__device__ float g_gih[(size_t)2 * Tz * Bz * Gz];   // LN'd input-side gates, [dir][t][b][4H]
__device__ float g_part[2 * Bz * Gz];               // raw hh gates, [dir][b][4H]
__device__ float g_h[2 * Bz * Hz];                  // hidden state per dir
__device__ float g_c[2 * Bz * Hz];                  // cell state per dir
__device__ unsigned g_cnt = 0;                      // grid barrier count
__device__ unsigned g_gen = 0;                      // grid barrier generation

// packed helpers
__device__ __forceinline__ ull dup2(float v) {
    unsigned u = __float_as_uint(v);
    return (ull)u | ((ull)u << 32);
}
__device__ __forceinline__ void ffma2(ull& acc, ull a, ull b) {
    asm("fma.rn.f32x2 %0, %1, %2, %0;" : "+l"(acc) : "l"(a), "l"(b));
}

// grid-wide barrier (sense-reversing). All NCTA CTAs co-resident (1 wave).
__device__ __forceinline__ void gbar() {
    __syncthreads();
    if (threadIdx.x == 0) {
        unsigned gen = *(volatile unsigned*)&g_gen;
        __threadfence();
        unsigned old = atomicAdd(&g_cnt, 1u);
        if (old == NCTA - 1) {
            atomicExch(&g_cnt, 0u);
            __threadfence();
            atomicAdd(&g_gen, 1u);
        } else {
            while (*(volatile unsigned*)&g_gen == gen) __nanosleep(64);
        }
        __threadfence();
    }
    __syncthreads();
}

// ---------------- input-side GEMM: raw = x @ W_ih^T + b_ih (both dirs) ----------------
// M = T*B = 32768 (row r = t*64+b; bwd reads x at T-1-t), N = 4096, K = 1024.
// 128x128 tile, BK=8, 256 threads, 8x8 microtile via packed f32x2 FMA.
__global__ __launch_bounds__(256)
void gemm_ih_kernel(const float* __restrict__ x,
                    const float* __restrict__ w_f, const float* __restrict__ bias_f,
                    const float* __restrict__ w_b, const float* __restrict__ bias_b) {
    const int dir = blockIdx.z;
    const float* __restrict__ W    = dir ? w_b : w_f;
    const float* __restrict__ bias = dir ? bias_b : bias_f;
    const int row0 = blockIdx.y * 128;
    const int col0 = blockIdx.x * 128;
    const int tid = threadIdx.x;

    __shared__ ull   AsD[8][130];   // A rows, value-duplicated pairs, [k][row]
    __shared__ float Bsf[8][132];   // B, [k][col]; 132 floats = 66 ull per row (16B aligned)

    const int lrow = tid >> 1;          // 0..127
    const int lk   = (tid & 1) * 4;     // 0 or 4
    const int arow = row0 + lrow;
    const int tt = arow >> 6;
    const int bb = arow & 63;
    const int tsrc = dir ? (Tz - 1 - tt) : tt;
    const float* aptr = x + ((size_t)bb * Tz + tsrc) * Dz + lk;
    const float* bptr = W + (size_t)(col0 + lrow) * Dz + lk;

    const int tx = tid & 15;
    const int ty = tid >> 4;

    ull acc[8][4];
#pragma unroll
    for (int i = 0; i < 8; i++)
#pragma unroll
        for (int p = 0; p < 4; p++) acc[i][p] = 0ull;

    float4 av = *(const float4*)(aptr);
    float4 bv = *(const float4*)(bptr);

    for (int k0 = 0; k0 < Dz; k0 += 8) {
        AsD[lk + 0][lrow] = dup2(av.x); AsD[lk + 1][lrow] = dup2(av.y);
        AsD[lk + 2][lrow] = dup2(av.z); AsD[lk + 3][lrow] = dup2(av.w);
        Bsf[lk + 0][lrow] = bv.x; Bsf[lk + 1][lrow] = bv.y;
        Bsf[lk + 2][lrow] = bv.z; Bsf[lk + 3][lrow] = bv.w;
        __syncthreads();
        if (k0 + 8 < Dz) {
            av = *(const float4*)(aptr + k0 + 8);
            bv = *(const float4*)(bptr + k0 + 8);
        }
        const ull* bsp = (const ull*)&Bsf[0][0];   // row kk at kk*66
#pragma unroll
        for (int kk = 0; kk < 8; kk++) {
            ull a[8], b[4];
#pragma unroll
            for (int i = 0; i < 4; i++) {
                a[i]     = AsD[kk][ty * 4 + i];
                a[4 + i] = AsD[kk][64 + ty * 4 + i];
            }
            b[0] = bsp[kk * 66 + tx * 2 + 0];
            b[1] = bsp[kk * 66 + tx * 2 + 1];
            b[2] = bsp[kk * 66 + 32 + tx * 2 + 0];
            b[3] = bsp[kk * 66 + 32 + tx * 2 + 1];
#pragma unroll
            for (int i = 0; i < 8; i++)
#pragma unroll
                for (int p = 0; p < 4; p++)
                    ffma2(acc[i][p], a[i], b[p]);
        }
        __syncthreads();
    }

    float* outbase = g_gih + (size_t)dir * (Tz * Bz) * Gz;
#pragma unroll
    for (int i = 0; i < 8; i++) {
        int r = row0 + ((i < 4) ? (ty * 4 + i) : (64 + ty * 4 + i - 4));
        float* orow = outbase + (size_t)r * Gz;
#pragma unroll
        for (int p = 0; p < 4; p++) {
            int c = col0 + ((p < 2) ? (tx * 4 + p * 2) : (64 + tx * 4 + (p - 2) * 2));
            union { ull u; float2 f; } cv; cv.u = acc[i][p];
            orow[c + 0] = cv.f.x + bias[c + 0];
            orow[c + 1] = cv.f.y + bias[c + 1];
        }
    }
}

// ---------------- LayerNorm (in place) over 4096 gate dim for g_gih ----------------
__global__ void ln_ih_kernel(const float* __restrict__ gain_f, const float* __restrict__ beta_f,
                             const float* __restrict__ gain_b, const float* __restrict__ beta_b) {
    const int row = blockIdx.x;          // dir*32768 + r
    const int dir = row >> 15;
    const float* __restrict__ gain = dir ? gain_b : gain_f;
    const float* __restrict__ beta = dir ? beta_b : beta_f;
    float* p = g_gih + (size_t)row * Gz;
    const int tid = threadIdx.x;

    float4 v[4];
    float sum = 0.f, sq = 0.f;
#pragma unroll
    for (int g = 0; g < 4; g++) {
        v[g] = *(const float4*)(p + g * 1024 + tid * 4);
        sum += v[g].x + v[g].y + v[g].z + v[g].w;
        sq  += v[g].x * v[g].x + v[g].y * v[g].y + v[g].z * v[g].z + v[g].w * v[g].w;
    }
    __shared__ float red[512];
    red[tid] = sum; red[256 + tid] = sq;
    __syncthreads();
    for (int s = 128; s > 0; s >>= 1) {
        if (tid < s) { red[tid] += red[tid + s]; red[256 + tid] += red[256 + tid + s]; }
        __syncthreads();
    }
    float mu = red[0] * (1.f / Gz);
    float var = red[256] * (1.f / Gz) - mu * mu;
    float sc = rsqrtf(var + EPSz);
#pragma unroll
    for (int g = 0; g < 4; g++) {
        int c = g * 1024 + tid * 4;
        float4 gv = *(const float4*)(gain + c);
        float4 bvv = *(const float4*)(beta + c);
        float4 o;
        o.x = (v[g].x - mu) * sc * gv.x + bvv.x;
        o.y = (v[g].y - mu) * sc * gv.y + bvv.y;
        o.z = (v[g].z - mu) * sc * gv.z + bvv.z;
        o.w = (v[g].w - mu) * sc * gv.w + bvv.w;
        *(float4*)(p + c) = o;
    }
}

// ---------------- persistent recurrence: 512 steps, 128 CTAs, grid barriers ----------------
// phase A: CTA (dir, ct) computes raw hh-gates tile [64 batch x 64 cols], K=1024.
// phase B: CTA (dir, b) does LN over 4096 + LSTM pointwise, updates h/c, writes out.
__global__ __launch_bounds__(256)
void lstm_persistent(const float* __restrict__ whh_f, const float* __restrict__ whh_b,
                     const float* __restrict__ bhh_f, const float* __restrict__ ghh_f,
                     const float* __restrict__ behh_f,
                     const float* __restrict__ bhh_b, const float* __restrict__ ghh_b,
                     const float* __restrict__ behh_b,
                     const float* __restrict__ fwd_init, const float* __restrict__ bwd_init,
                     float* __restrict__ out) {
    const int tid = threadIdx.x;
    const int bid = blockIdx.x;

    // init h0/c0
    for (int i = bid * 256 + tid; i < 2 * Bz * Hz; i += NCTA * 256) {
        int dir0 = i >> 16;                 // Bz*Hz = 65536
        int j = i & (Hz - 1);
        const float* init = dir0 ? bwd_init : fwd_init;
        g_h[i] = init[j];
        g_c[i] = init[Hz + j];
    }

    __shared__ ull   AsD[16][66];   // h rows dup-packed, [k][row]
    __shared__ float Bsf[16][66];   // W, [k][col]; 66 floats = 33 ull per row
    __shared__ float red[512];

    const int dir = bid >> 6;
    const int ct  = bid & 63;
    const int col0 = ct * 64;
    const float* __restrict__ W = dir ? whh_b : whh_f;

    const int lrow = tid >> 2;              // 0..63
    const int lk   = (tid & 3) * 4;         // 0,4,8,12
    const float* abase = g_h + (size_t)dir * Bz * Hz + (size_t)lrow * Hz + lk;
    const float* bbase = W + (size_t)(col0 + lrow) * Hz + lk;

    const int tx = tid & 15;
    const int ty = tid >> 4;

    // cell-phase parameters (same (dir, b=ct) decomposition)
    const int cb = ct;
    const float* __restrict__ bhh  = dir ? bhh_b  : bhh_f;
    const float* __restrict__ ghh  = dir ? ghh_b  : ghh_f;
    const float* __restrict__ behh = dir ? behh_b : behh_f;
    float* prow_mine = g_part + ((size_t)dir * Bz + cb) * Gz;
    float* cptr = g_c + ((size_t)dir * Bz + cb) * Hz + tid * 4;
    float* hptr = g_h + ((size_t)dir * Bz + cb) * Hz + tid * 4;
    float* o2   = out + (size_t)Bz * Tz * 2 * Hz + (size_t)cb * (2 * Hz) + dir * Hz + tid * 4;

    gbar();   // h0/c0 visible everywhere

    for (int t = 0; t < Tz; t++) {
        // ================= phase A: raw = h @ Whh^T =================
        ull acc[4][2];
#pragma unroll
        for (int i = 0; i < 4; i++) { acc[i][0] = 0ull; acc[i][1] = 0ull; }

        float4 av = *(const float4*)(abase);
        float4 bv = *(const float4*)(bbase);

        for (int k0 = 0; k0 < Hz; k0 += 16) {
            AsD[lk + 0][lrow] = dup2(av.x); AsD[lk + 1][lrow] = dup2(av.y);
            AsD[lk + 2][lrow] = dup2(av.z); AsD[lk + 3][lrow] = dup2(av.w);
            Bsf[lk + 0][lrow] = bv.x; Bsf[lk + 1][lrow] = bv.y;
            Bsf[lk + 2][lrow] = bv.z; Bsf[lk + 3][lrow] = bv.w;
            __syncthreads();
            if (k0 + 16 < Hz) {
                av = *(const float4*)(abase + k0 + 16);
                bv = *(const float4*)(bbase + k0 + 16);
            }
            const ull* bsp = (const ull*)&Bsf[0][0];   // row kk at kk*33
#pragma unroll
            for (int kk = 0; kk < 16; kk++) {
                ull a0 = AsD[kk][ty * 4 + 0];
                ull a1 = AsD[kk][ty * 4 + 1];
                ull a2 = AsD[kk][ty * 4 + 2];
                ull a3 = AsD[kk][ty * 4 + 3];
                ull b0 = bsp[kk * 33 + tx * 2 + 0];
                ull b1 = bsp[kk * 33 + tx * 2 + 1];
                ffma2(acc[0][0], a0, b0); ffma2(acc[0][1], a0, b1);
                ffma2(acc[1][0], a1, b0); ffma2(acc[1][1], a1, b1);
                ffma2(acc[2][0], a2, b0); ffma2(acc[2][1], a2, b1);
                ffma2(acc[3][0], a3, b0); ffma2(acc[3][1], a3, b1);
            }
            __syncthreads();
        }
#pragma unroll
        for (int i = 0; i < 4; i++) {
            float* orow = g_part + ((size_t)dir * Bz + ty * 4 + i) * Gz + col0 + tx * 4;
            union { ull u; float2 f; } c0, c1;
            c0.u = acc[i][0]; c1.u = acc[i][1];
            *(float4*)orow = make_float4(c0.f.x, c0.f.y, c1.f.x, c1.f.y);
        }

        gbar();   // all raw gate tiles visible

        // ================= phase B: LN + LSTM cell =================
        {
            float4 raw[4];
            float sum = 0.f, sq = 0.f;
#pragma unroll
            for (int g = 0; g < 4; g++) {
                int c = g * 1024 + tid * 4;
                float4 r = *(const float4*)(prow_mine + c);
                float4 bh = *(const float4*)(bhh + c);
                r.x += bh.x; r.y += bh.y; r.z += bh.z; r.w += bh.w;
                raw[g] = r;
                sum += r.x + r.y + r.z + r.w;
                sq  += r.x * r.x + r.y * r.y + r.z * r.z + r.w * r.w;
            }
            red[tid] = sum; red[256 + tid] = sq;
            __syncthreads();
            for (int s = 128; s > 0; s >>= 1) {
                if (tid < s) { red[tid] += red[tid + s]; red[256 + tid] += red[256 + tid + s]; }
                __syncthreads();
            }
            float mu = red[0] * (1.f / Gz);
            float var = red[256] * (1.f / Gz) - mu * mu;
            float sc = rsqrtf(var + EPSz);

            const float* gih = g_gih + ((size_t)dir * Tz * Bz + (size_t)t * Bz + cb) * Gz;
            float gate[4][4];
#pragma unroll
            for (int g = 0; g < 4; g++) {
                int c = g * 1024 + tid * 4;
                float4 gi = *(const float4*)(gih + c);
                float4 gg = *(const float4*)(ghh + c);
                float4 be = *(const float4*)(behh + c);
                gate[g][0] = gi.x + (raw[g].x - mu) * sc * gg.x + be.x;
                gate[g][1] = gi.y + (raw[g].y - mu) * sc * gg.y + be.y;
                gate[g][2] = gi.z + (raw[g].z - mu) * sc * gg.z + be.z;
                gate[g][3] = gi.w + (raw[g].w - mu) * sc * gg.w + be.w;
            }
            float* optr = out + ((size_t)cb * Tz + t) * (2 * Hz) + dir * Hz + tid * 4;
#pragma unroll
            for (int q = 0; q < 4; q++) {
                float iv = 1.f / (1.f + expf(-gate[0][q]));
                float fv = 1.f / (1.f + expf(-gate[1][q]));
                float gv = tanhf(gate[2][q]);
                float ov = 1.f / (1.f + expf(-gate[3][q]));
                float cn = fv * cptr[q] + iv * gv;
                float hn = ov * tanhf(cn);
                cptr[q] = cn;
                hptr[q] = hn;
                optr[q] = hn;
                if (t == Tz - 1) o2[q] = hn;
            }
        }

        gbar();   // new h visible before next step's phase A
    }
}

// ---------------- launch ----------------
extern "C" void kernel_launch(void* const* d_in, const int* in_sizes, int n_in,
                              void* d_out, int out_size) {
    const float* x      = (const float*)d_in[0];
    const float* wih_f  = (const float*)d_in[1];
    const float* whh_f  = (const float*)d_in[2];
    const float* bih_f  = (const float*)d_in[3];
    const float* bhh_f  = (const float*)d_in[4];
    const float* gih_f  = (const float*)d_in[5];
    const float* beih_f = (const float*)d_in[6];
    const float* ghh_f  = (const float*)d_in[7];
    const float* behh_f = (const float*)d_in[8];
    const float* wih_b  = (const float*)d_in[9];
    const float* whh_b  = (const float*)d_in[10];
    const float* bih_b  = (const float*)d_in[11];
    const float* bhh_b  = (const float*)d_in[12];
    const float* gih_b  = (const float*)d_in[13];
    const float* beih_b = (const float*)d_in[14];
    const float* ghh_b  = (const float*)d_in[15];
    const float* behh_b = (const float*)d_in[16];
    const float* fwd_init = (const float*)d_in[17];
    const float* bwd_init = (const float*)d_in[18];
    float* out = (float*)d_out;

    gemm_ih_kernel<<<dim3(32, 256, 2), 256>>>(x, wih_f, bih_f, wih_b, bih_b);
    ln_ih_kernel<<<65536, 256>>>(gih_f, beih_f, gih_b, beih_b);
    lstm_persistent<<<NCTA, 256>>>(whh_f, whh_b,
                                   bhh_f, ghh_f, behh_f,
                                   bhh_b, ghh_b, behh_b,
                                   fwd_init, bwd_init, out);
}

// round 4
// speedup vs baseline: 1.3377x; 1.3377x over previous
#include <cuda_runtime.h>
#include <math.h>

#define Bz 64
#define Tz 512
#define Dz 1024
#define Hz 1024
#define Gz 4096          // 4*H
#define EPSz 1e-5f
#define NCTA 128

typedef unsigned long long ull;

// ---------------- scratch (device globals; no runtime allocation) ----------------
__device__ float g_gih[(size_t)2 * Tz * Bz * Gz];   // LN'd input-side gates, [dir][t][b][4H]
__device__ float g_wt[(size_t)2 * Hz * Gz];         // W_hh transposed: [dir][k][col]
__device__ float g_part[4 * 2 * Bz * Gz];           // split-K partials, [ks][dir][b][4H]
__device__ float g_h[2 * Bz * Hz];                  // hidden state per dir
__device__ float g_c[2 * Bz * Hz];                  // cell state per dir
__device__ unsigned g_cnt = 0;                      // grid barrier count
__device__ unsigned g_gen = 0;                      // grid barrier generation

// packed helpers
__device__ __forceinline__ ull dup2(float v) {
    unsigned u = __float_as_uint(v);
    return (ull)u | ((ull)u << 32);
}
__device__ __forceinline__ void ffma2(ull& acc, ull a, ull b) {
    asm("fma.rn.f32x2 %0, %1, %2, %0;" : "+l"(acc) : "l"(a), "l"(b));
}

// grid-wide barrier (sense-reversing). All NCTA CTAs co-resident (1 wave).
__device__ __forceinline__ void gbar() {
    __syncthreads();
    if (threadIdx.x == 0) {
        unsigned gen = *(volatile unsigned*)&g_gen;
        __threadfence();
        unsigned old = atomicAdd(&g_cnt, 1u);
        if (old == NCTA - 1) {
            atomicExch(&g_cnt, 0u);
            __threadfence();
            atomicAdd(&g_gen, 1u);
        } else {
            while (*(volatile unsigned*)&g_gen == gen) __nanosleep(32);
        }
        __threadfence();
    }
    __syncthreads();
}

// ---------------- transpose W_hh -> g_wt[dir][k][col] ----------------
__global__ void transpose_w_kernel(const float* __restrict__ whh_f,
                                   const float* __restrict__ whh_b) {
    const int dir = blockIdx.z;
    const float* __restrict__ W = dir ? whh_b : whh_f;   // [col][k], 4096 x 1024
    const int k0 = blockIdx.x * 32;
    const int c0 = blockIdx.y * 32;
    __shared__ float t[32][33];
    const int tx = threadIdx.x & 31;
    const int ty0 = (threadIdx.x >> 5) * 4;
#pragma unroll
    for (int i = 0; i < 4; i++) {
        int r = ty0 + i;   // col index offset
        t[r][tx] = W[(size_t)(c0 + r) * Hz + k0 + tx];
    }
    __syncthreads();
    float* out = g_wt + (size_t)dir * Hz * Gz;
#pragma unroll
    for (int i = 0; i < 4; i++) {
        int r = ty0 + i;   // k index offset
        out[(size_t)(k0 + r) * Gz + c0 + tx] = t[tx][r];
    }
}

// ---------------- input-side GEMM: raw = x @ W_ih^T + b_ih (both dirs) ----------------
__global__ __launch_bounds__(256)
void gemm_ih_kernel(const float* __restrict__ x,
                    const float* __restrict__ w_f, const float* __restrict__ bias_f,
                    const float* __restrict__ w_b, const float* __restrict__ bias_b) {
    const int dir = blockIdx.z;
    const float* __restrict__ W    = dir ? w_b : w_f;
    const float* __restrict__ bias = dir ? bias_b : bias_f;
    const int row0 = blockIdx.y * 128;
    const int col0 = blockIdx.x * 128;
    const int tid = threadIdx.x;

    __shared__ ull   AsD[8][130];
    __shared__ float Bsf[8][132];

    const int lrow = tid >> 1;
    const int lk   = (tid & 1) * 4;
    const int arow = row0 + lrow;
    const int tt = arow >> 6;
    const int bb = arow & 63;
    const int tsrc = dir ? (Tz - 1 - tt) : tt;
    const float* aptr = x + ((size_t)bb * Tz + tsrc) * Dz + lk;
    const float* bptr = W + (size_t)(col0 + lrow) * Dz + lk;

    const int tx = tid & 15;
    const int ty = tid >> 4;

    ull acc[8][4];
#pragma unroll
    for (int i = 0; i < 8; i++)
#pragma unroll
        for (int p = 0; p < 4; p++) acc[i][p] = 0ull;

    float4 av = *(const float4*)(aptr);
    float4 bv = *(const float4*)(bptr);

    for (int k0 = 0; k0 < Dz; k0 += 8) {
        AsD[lk + 0][lrow] = dup2(av.x); AsD[lk + 1][lrow] = dup2(av.y);
        AsD[lk + 2][lrow] = dup2(av.z); AsD[lk + 3][lrow] = dup2(av.w);
        Bsf[lk + 0][lrow] = bv.x; Bsf[lk + 1][lrow] = bv.y;
        Bsf[lk + 2][lrow] = bv.z; Bsf[lk + 3][lrow] = bv.w;
        __syncthreads();
        if (k0 + 8 < Dz) {
            av = *(const float4*)(aptr + k0 + 8);
            bv = *(const float4*)(bptr + k0 + 8);
        }
        const ull* bsp = (const ull*)&Bsf[0][0];
#pragma unroll
        for (int kk = 0; kk < 8; kk++) {
            ull a[8], b[4];
#pragma unroll
            for (int i = 0; i < 4; i++) {
                a[i]     = AsD[kk][ty * 4 + i];
                a[4 + i] = AsD[kk][64 + ty * 4 + i];
            }
            b[0] = bsp[kk * 66 + tx * 2 + 0];
            b[1] = bsp[kk * 66 + tx * 2 + 1];
            b[2] = bsp[kk * 66 + 32 + tx * 2 + 0];
            b[3] = bsp[kk * 66 + 32 + tx * 2 + 1];
#pragma unroll
            for (int i = 0; i < 8; i++)
#pragma unroll
                for (int p = 0; p < 4; p++)
                    ffma2(acc[i][p], a[i], b[p]);
        }
        __syncthreads();
    }

    float* outbase = g_gih + (size_t)dir * (Tz * Bz) * Gz;
#pragma unroll
    for (int i = 0; i < 8; i++) {
        int r = row0 + ((i < 4) ? (ty * 4 + i) : (64 + ty * 4 + i - 4));
        float* orow = outbase + (size_t)r * Gz;
#pragma unroll
        for (int p = 0; p < 4; p++) {
            int c = col0 + ((p < 2) ? (tx * 4 + p * 2) : (64 + tx * 4 + (p - 2) * 2));
            union { ull u; float2 f; } cv; cv.u = acc[i][p];
            orow[c + 0] = cv.f.x + bias[c + 0];
            orow[c + 1] = cv.f.y + bias[c + 1];
        }
    }
}

// ---------------- LayerNorm (in place) over 4096 gate dim for g_gih ----------------
__global__ void ln_ih_kernel(const float* __restrict__ gain_f, const float* __restrict__ beta_f,
                             const float* __restrict__ gain_b, const float* __restrict__ beta_b) {
    const int row = blockIdx.x;
    const int dir = row >> 15;
    const float* __restrict__ gain = dir ? gain_b : gain_f;
    const float* __restrict__ beta = dir ? beta_b : beta_f;
    float* p = g_gih + (size_t)row * Gz;
    const int tid = threadIdx.x;

    float4 v[4];
    float sum = 0.f, sq = 0.f;
#pragma unroll
    for (int g = 0; g < 4; g++) {
        v[g] = *(const float4*)(p + g * 1024 + tid * 4);
        sum += v[g].x + v[g].y + v[g].z + v[g].w;
        sq  += v[g].x * v[g].x + v[g].y * v[g].y + v[g].z * v[g].z + v[g].w * v[g].w;
    }
    __shared__ float red[512];
    red[tid] = sum; red[256 + tid] = sq;
    __syncthreads();
    for (int s = 128; s > 0; s >>= 1) {
        if (tid < s) { red[tid] += red[tid + s]; red[256 + tid] += red[256 + tid + s]; }
        __syncthreads();
    }
    float mu = red[0] * (1.f / Gz);
    float var = red[256] * (1.f / Gz) - mu * mu;
    float sc = rsqrtf(var + EPSz);
#pragma unroll
    for (int g = 0; g < 4; g++) {
        int c = g * 1024 + tid * 4;
        float4 gv = *(const float4*)(gain + c);
        float4 bvv = *(const float4*)(beta + c);
        float4 o;
        o.x = (v[g].x - mu) * sc * gv.x + bvv.x;
        o.y = (v[g].y - mu) * sc * gv.y + bvv.y;
        o.z = (v[g].z - mu) * sc * gv.z + bvv.z;
        o.w = (v[g].w - mu) * sc * gv.w + bvv.w;
        *(float4*)(p + c) = o;
    }
}

// ---------------- persistent recurrence ----------------
// Phase A CTA map: bid = dir*64 + nt*4 + ks  (nt: 16 tiles of 256 cols, ks: 4 slices of K=256)
//   tile: M=64 batches x N=256 cols, K=256; microtile 8x8 per thread (256 thr: tx 0..31, ty 0..7)
// Phase B CTA map: dir = bid>>6, b = bid&63 — LN(sum of 4 partials)+cell for one (dir,batch).
#define SM_AS  (2 * 32 * 64)       // ull count
#define SM_BS  (2 * 32 * 256)      // float count
#define SMEM_BYTES (SM_AS * 8 + SM_BS * 4 + 512 * 4)

__global__ __launch_bounds__(256, 1)
void lstm_persistent(const float* __restrict__ bhh_f, const float* __restrict__ ghh_f,
                     const float* __restrict__ behh_f,
                     const float* __restrict__ bhh_b, const float* __restrict__ ghh_b,
                     const float* __restrict__ behh_b,
                     const float* __restrict__ fwd_init, const float* __restrict__ bwd_init,
                     float* __restrict__ out) {
    extern __shared__ char smem[];
    ull*   As  = (ull*)smem;                              // [2][32][64]
    float* Bs  = (float*)(smem + SM_AS * 8);              // [2][32][256]
    float* red = (float*)(smem + SM_AS * 8 + SM_BS * 4);  // [512]

    const int tid = threadIdx.x;
    const int bid = blockIdx.x;

    // init h0/c0
    for (int i = bid * 256 + tid; i < 2 * Bz * Hz; i += NCTA * 256) {
        int dir0 = i >> 16;
        int j = i & (Hz - 1);
        const float* init = dir0 ? bwd_init : fwd_init;
        g_h[i] = init[j];
        g_c[i] = init[Hz + j];
    }

    // ---- phase A identifiers ----
    const int dirA = bid >> 6;
    const int nt   = (bid & 63) >> 2;
    const int ks   = bid & 3;
    const int col0 = nt * 256;
    const int kbase = ks * 256;

    const int tx = tid & 31;       // col-group (8 cols)
    const int ty = tid >> 5;       // row-group (8 rows)

    // A loader: row = tid>>2 (0..63), k-offset = (tid&3)*8
    const float* hbase = g_h + (size_t)dirA * (Bz * Hz) + (size_t)(tid >> 2) * Hz
                         + kbase + (tid & 3) * 8;
    // B loader: k' = tid>>3 (0..31), col-offset = (tid&7)*32
    const float* wtbase = g_wt + (size_t)dirA * (Hz * Gz)
                          + (size_t)(kbase + (tid >> 3)) * Gz + col0 + (tid & 7) * 32;
    // A STS target: k = (tid&3)*8 + j, row = tid>>2
    const int aSk = (tid & 3) * 8;
    const int aSr = tid >> 2;
    // B STS target: k = tid>>3, col = (tid&7)*32
    const int bSoff = (tid >> 3) * 256 + (tid & 7) * 32;

    // ---- phase B identifiers ----
    const int dirB = bid >> 6;
    const int cb   = bid & 63;
    const float* __restrict__ bhh  = dirB ? bhh_b  : bhh_f;
    const float* __restrict__ ghh  = dirB ? ghh_b  : ghh_f;
    const float* __restrict__ behh = dirB ? behh_b : behh_f;
    float* cptr = g_c + ((size_t)dirB * Bz + cb) * Hz + tid * 4;
    float* hptr = g_h + ((size_t)dirB * Bz + cb) * Hz + tid * 4;
    float* o2   = out + (size_t)Bz * Tz * 2 * Hz + (size_t)cb * (2 * Hz) + dirB * Hz + tid * 4;

    gbar();   // h0/c0 visible everywhere

    for (int t = 0; t < Tz; t++) {
        // ================= phase A: part[ks] = h @ Whh^T (slice) =================
        ull acc[8][4];
#pragma unroll
        for (int i = 0; i < 8; i++)
#pragma unroll
            for (int p = 0; p < 4; p++) acc[i][p] = 0ull;

        float4 avA, avA2;
        float4 bvB[8];
        // stage chunk 0
        avA  = *(const float4*)(hbase);
        avA2 = *(const float4*)(hbase + 4);
#pragma unroll
        for (int q = 0; q < 8; q++)
            bvB[q] = *(const float4*)(wtbase + q * 4);
        {
            ull* as = As + aSk * 64 + aSr;
            as[0*64] = dup2(avA.x);  as[1*64] = dup2(avA.y);
            as[2*64] = dup2(avA.z);  as[3*64] = dup2(avA.w);
            as[4*64] = dup2(avA2.x); as[5*64] = dup2(avA2.y);
            as[6*64] = dup2(avA2.z); as[7*64] = dup2(avA2.w);
            float* bs = Bs + bSoff;
#pragma unroll
            for (int q = 0; q < 8; q++)
                *(float4*)(bs + q * 4) = bvB[q];
        }
        __syncthreads();

        for (int c = 0; c < 8; c++) {
            const int cur = c & 1;
            if (c < 7) {
                avA  = *(const float4*)(hbase + (c + 1) * 32);
                avA2 = *(const float4*)(hbase + (c + 1) * 32 + 4);
#pragma unroll
                for (int q = 0; q < 8; q++)
                    bvB[q] = *(const float4*)(wtbase + (size_t)(c + 1) * 32 * Gz + q * 4);
            }
            const ull*   asb = As + cur * 2048;
            const float* bsb = Bs + cur * 8192;
#pragma unroll 4
            for (int kk = 0; kk < 32; kk++) {
                const ull* ar = asb + kk * 64 + ty * 8;
                ull a0 = ar[0], a1 = ar[1], a2 = ar[2], a3 = ar[3];
                ull a4 = ar[4], a5 = ar[5], a6 = ar[6], a7 = ar[7];
                const ull* br = (const ull*)(bsb + kk * 256) + tx * 4;
                ull b0 = br[0], b1 = br[1], b2 = br[2], b3 = br[3];
                ffma2(acc[0][0], a0, b0); ffma2(acc[0][1], a0, b1);
                ffma2(acc[0][2], a0, b2); ffma2(acc[0][3], a0, b3);
                ffma2(acc[1][0], a1, b0); ffma2(acc[1][1], a1, b1);
                ffma2(acc[1][2], a1, b2); ffma2(acc[1][3], a1, b3);
                ffma2(acc[2][0], a2, b0); ffma2(acc[2][1], a2, b1);
                ffma2(acc[2][2], a2, b2); ffma2(acc[2][3], a2, b3);
                ffma2(acc[3][0], a3, b0); ffma2(acc[3][1], a3, b1);
                ffma2(acc[3][2], a3, b2); ffma2(acc[3][3], a3, b3);
                ffma2(acc[4][0], a4, b0); ffma2(acc[4][1], a4, b1);
                ffma2(acc[4][2], a4, b2); ffma2(acc[4][3], a4, b3);
                ffma2(acc[5][0], a5, b0); ffma2(acc[5][1], a5, b1);
                ffma2(acc[5][2], a5, b2); ffma2(acc[5][3], a5, b3);
                ffma2(acc[6][0], a6, b0); ffma2(acc[6][1], a6, b1);
                ffma2(acc[6][2], a6, b2); ffma2(acc[6][3], a6, b3);
                ffma2(acc[7][0], a7, b0); ffma2(acc[7][1], a7, b1);
                ffma2(acc[7][2], a7, b2); ffma2(acc[7][3], a7, b3);
            }
            if (c < 7) {
                const int nxt = cur ^ 1;
                ull* as = As + nxt * 2048 + aSk * 64 + aSr;
                as[0*64] = dup2(avA.x);  as[1*64] = dup2(avA.y);
                as[2*64] = dup2(avA.z);  as[3*64] = dup2(avA.w);
                as[4*64] = dup2(avA2.x); as[5*64] = dup2(avA2.y);
                as[6*64] = dup2(avA2.z); as[7*64] = dup2(avA2.w);
                float* bs = Bs + nxt * 8192 + bSoff;
#pragma unroll
                for (int q = 0; q < 8; q++)
                    *(float4*)(bs + q * 4) = bvB[q];
                __syncthreads();
            }
        }

        // epilogue: store 8x8 tile to g_part
        {
            float* pbase = g_part + (size_t)(ks * 2 + dirA) * Bz * Gz;
#pragma unroll
            for (int i = 0; i < 8; i++) {
                float* dst = pbase + (size_t)(ty * 8 + i) * Gz + col0 + tx * 8;
                union { ull u; float2 f; } c0u, c1u, c2u, c3u;
                c0u.u = acc[i][0]; c1u.u = acc[i][1];
                c2u.u = acc[i][2]; c3u.u = acc[i][3];
                *(float4*)dst       = make_float4(c0u.f.x, c0u.f.y, c1u.f.x, c1u.f.y);
                *(float4*)(dst + 4) = make_float4(c2u.f.x, c2u.f.y, c3u.f.x, c3u.f.y);
            }
        }

        gbar();   // all partial tiles visible

        // ================= phase B: sum partials + LN + LSTM cell =================
        {
            float4 raw[4];
            float sum = 0.f, sq = 0.f;
#pragma unroll
            for (int g = 0; g < 4; g++) {
                int c = g * 1024 + tid * 4;
                float4 r = make_float4(0.f, 0.f, 0.f, 0.f);
#pragma unroll
                for (int s = 0; s < 4; s++) {
                    float4 pv = *(const float4*)(g_part + ((size_t)(s * 2 + dirB) * Bz + cb) * Gz + c);
                    r.x += pv.x; r.y += pv.y; r.z += pv.z; r.w += pv.w;
                }
                float4 bh = *(const float4*)(bhh + c);
                r.x += bh.x; r.y += bh.y; r.z += bh.z; r.w += bh.w;
                raw[g] = r;
                sum += r.x + r.y + r.z + r.w;
                sq  += r.x * r.x + r.y * r.y + r.z * r.z + r.w * r.w;
            }
            red[tid] = sum; red[256 + tid] = sq;
            __syncthreads();
            for (int s = 128; s > 0; s >>= 1) {
                if (tid < s) { red[tid] += red[tid + s]; red[256 + tid] += red[256 + tid + s]; }
                __syncthreads();
            }
            float mu = red[0] * (1.f / Gz);
            float var = red[256] * (1.f / Gz) - mu * mu;
            float sc = rsqrtf(var + EPSz);

            const float* gih = g_gih + ((size_t)dirB * Tz * Bz + (size_t)t * Bz + cb) * Gz;
            float gate[4][4];
#pragma unroll
            for (int g = 0; g < 4; g++) {
                int c = g * 1024 + tid * 4;
                float4 gi = *(const float4*)(gih + c);
                float4 gg = *(const float4*)(ghh + c);
                float4 be = *(const float4*)(behh + c);
                gate[g][0] = gi.x + (raw[g].x - mu) * sc * gg.x + be.x;
                gate[g][1] = gi.y + (raw[g].y - mu) * sc * gg.y + be.y;
                gate[g][2] = gi.z + (raw[g].z - mu) * sc * gg.z + be.z;
                gate[g][3] = gi.w + (raw[g].w - mu) * sc * gg.w + be.w;
            }
            float* optr = out + ((size_t)cb * Tz + t) * (2 * Hz) + dirB * Hz + tid * 4;
#pragma unroll
            for (int q = 0; q < 4; q++) {
                float iv = 1.f / (1.f + expf(-gate[0][q]));
                float fv = 1.f / (1.f + expf(-gate[1][q]));
                float gv = tanhf(gate[2][q]);
                float ov = 1.f / (1.f + expf(-gate[3][q]));
                float cn = fv * cptr[q] + iv * gv;
                float hn = ov * tanhf(cn);
                cptr[q] = cn;
                hptr[q] = hn;
                optr[q] = hn;
                if (t == Tz - 1) o2[q] = hn;
            }
        }

        gbar();   // new h visible before next step's phase A
    }
}

// ---------------- launch ----------------
extern "C" void kernel_launch(void* const* d_in, const int* in_sizes, int n_in,
                              void* d_out, int out_size) {
    const float* x      = (const float*)d_in[0];
    const float* wih_f  = (const float*)d_in[1];
    const float* whh_f  = (const float*)d_in[2];
    const float* bih_f  = (const float*)d_in[3];
    const float* bhh_f  = (const float*)d_in[4];
    const float* gih_f  = (const float*)d_in[5];
    const float* beih_f = (const float*)d_in[6];
    const float* ghh_f  = (const float*)d_in[7];
    const float* behh_f = (const float*)d_in[8];
    const float* wih_b  = (const float*)d_in[9];
    const float* whh_b  = (const float*)d_in[10];
    const float* bih_b  = (const float*)d_in[11];
    const float* bhh_b  = (const float*)d_in[12];
    const float* gih_b  = (const float*)d_in[13];
    const float* beih_b = (const float*)d_in[14];
    const float* ghh_b  = (const float*)d_in[15];
    const float* behh_b = (const float*)d_in[16];
    const float* fwd_init = (const float*)d_in[17];
    const float* bwd_init = (const float*)d_in[18];
    float* out = (float*)d_out;

    static int smem_set = 0;
    if (!smem_set) {
        cudaFuncSetAttribute(lstm_persistent,
                             cudaFuncAttributeMaxDynamicSharedMemorySize, SMEM_BYTES);
        smem_set = 1;
    }

    transpose_w_kernel<<<dim3(32, 128, 2), 256>>>(whh_f, whh_b);
    gemm_ih_kernel<<<dim3(32, 256, 2), 256>>>(x, wih_f, bih_f, wih_b, bih_b);
    ln_ih_kernel<<<65536, 256>>>(gih_f, beih_f, gih_b, beih_b);
    lstm_persistent<<<NCTA, 256, SMEM_BYTES>>>(bhh_f, ghh_f, behh_f,
                                               bhh_b, ghh_b, behh_b,
                                               fwd_init, bwd_init, out);
}

// round 6
// speedup vs baseline: 2.3435x; 1.7519x over previous
#include <cuda_runtime.h>
#include <cuda_bf16.h>
#include <math.h>
#include <stdint.h>

#define Bz 64
#define Tz 512
#define Dz 1024
#define Hz 1024
#define Gz 4096          // 4*H
#define EPSz 1e-5f
#define NCTA 128

typedef unsigned long long ull;

// ---------------- scratch (device globals; no runtime allocation) ----------------
__device__ float g_gih[(size_t)2 * Tz * Bz * Gz];      // LN'd input gates [dir][t][b][4H]
// W_hh in mma.sync fragment layout: [dir][wn 0..255][kstep 0..63][128 words] (16 MB each)
__device__ __align__(16) unsigned g_wfh[(size_t)2 * 256 * 64 * 128];
__device__ __align__(16) unsigned g_wfl[(size_t)2 * 256 * 64 * 128];
// h in A-fragment layout: [dir][kstep 0..63][mt 0..3][128 words] (256 KB each)
__device__ __align__(16) unsigned g_hfh[2 * 64 * 4 * 128];
__device__ __align__(16) unsigned g_hfl[2 * 64 * 4 * 128];
__device__ float g_part[2 * 2 * Bz * Gz];              // [ks][dir][b][4H]
__device__ float g_c[2 * Bz * Hz];                     // cell state
__device__ unsigned g_cnt = 0;
__device__ unsigned g_gen = 0;

// ---------------- helpers ----------------
__device__ __forceinline__ ull dup2(float v) {
    unsigned u = __float_as_uint(v);
    return (ull)u | ((ull)u << 32);
}
__device__ __forceinline__ void ffma2(ull& acc, ull a, ull b) {
    asm("fma.rn.f32x2 %0, %1, %2, %0;" : "+l"(acc) : "l"(a), "l"(b));
}

__device__ __forceinline__ void split_bf16(float v, __nv_bfloat16& hi, __nv_bfloat16& lo) {
    hi = __float2bfloat16(v);
    lo = __float2bfloat16(v - __bfloat162float(hi));
}
__device__ __forceinline__ unsigned pack2(__nv_bfloat16 a, __nv_bfloat16 b) {
    return (unsigned)__bfloat16_as_ushort(a) | ((unsigned)__bfloat16_as_ushort(b) << 16);
}

// HMMA m16n8k16 bf16 row.col, f32 accumulate
__device__ __forceinline__ void mma16816(float* c, const uint4& a, unsigned b0, unsigned b1) {
    asm volatile(
        "mma.sync.aligned.m16n8k16.row.col.f32.bf16.bf16.f32 "
        "{%0,%1,%2,%3}, {%4,%5,%6,%7}, {%8,%9}, {%0,%1,%2,%3};"
        : "+f"(c[0]), "+f"(c[1]), "+f"(c[2]), "+f"(c[3])
        : "r"(a.x), "r"(a.y), "r"(a.z), "r"(a.w), "r"(b0), "r"(b1));
}

// grid-wide barrier (sense-reversing), all NCTA CTAs co-resident
__device__ __forceinline__ void gbar() {
    __syncthreads();
    if (threadIdx.x == 0) {
        unsigned gen = *(volatile unsigned*)&g_gen;
        __threadfence();
        unsigned old = atomicAdd(&g_cnt, 1u);
        if (old == NCTA - 1) {
            atomicExch(&g_cnt, 0u);
            __threadfence();
            atomicAdd(&g_gen, 1u);
        } else {
            while (*(volatile unsigned*)&g_gen == gen) __nanosleep(32);
        }
        __threadfence();
    }
    __syncthreads();
}

// ---------------- prep: W_hh -> bf16 hi/lo B-fragment images ----------------
// B-fragment block (wn, kstep) = 128 words; lane T holds words [T*4 .. T*4+3]:
//   q=0: n8-tile0 klo, q=1: n8-tile0 khi, q=2: n8-tile1 klo, q=3: n8-tile1 khi
//   element: col = wn*16 + (q>>1)*8 + T/4 ; kpair = (q&1)*4 + (T&3); k = kstep*16 + kpair*2
__global__ void prep_w_kernel(const float* __restrict__ whh_f, const float* __restrict__ whh_b) {
    int gid = blockIdx.x * 256 + threadIdx.x;     // 2*256*64*32 = 1,048,576
    int T     = gid & 31;
    int kstep = (gid >> 5) & 63;
    int wn    = (gid >> 11) & 255;
    int dir   = gid >> 19;
    const float* __restrict__ W = dir ? whh_b : whh_f;
    unsigned hw[4], lw[4];
#pragma unroll
    for (int q = 0; q < 4; q++) {
        int c = wn * 16 + (q >> 1) * 8 + (T >> 2);
        int k = kstep * 16 + ((q & 1) * 4 + (T & 3)) * 2;
        float2 v = *(const float2*)(W + (size_t)c * Hz + k);
        __nv_bfloat16 h0, l0, h1, l1;
        split_bf16(v.x, h0, l0);
        split_bf16(v.y, h1, l1);
        hw[q] = pack2(h0, h1);
        lw[q] = pack2(l0, l1);
    }
    size_t base = ((size_t)(dir * 256 + wn) * 64 + kstep) * 128 + T * 4;
    *(uint4*)&g_wfh[base] = make_uint4(hw[0], hw[1], hw[2], hw[3]);
    *(uint4*)&g_wfl[base] = make_uint4(lw[0], lw[1], lw[2], lw[3]);
}

// ---------------- input-side GEMM (FFMA2, unchanged) ----------------
__global__ __launch_bounds__(256)
void gemm_ih_kernel(const float* __restrict__ x,
                    const float* __restrict__ w_f, const float* __restrict__ bias_f,
                    const float* __restrict__ w_b, const float* __restrict__ bias_b) {
    const int dir = blockIdx.z;
    const float* __restrict__ W    = dir ? w_b : w_f;
    const float* __restrict__ bias = dir ? bias_b : bias_f;
    const int row0 = blockIdx.y * 128;
    const int col0 = blockIdx.x * 128;
    const int tid = threadIdx.x;

    __shared__ ull   AsD[8][130];
    __shared__ float Bsf[8][132];

    const int lrow = tid >> 1;
    const int lk   = (tid & 1) * 4;
    const int arow = row0 + lrow;
    const int tt = arow >> 6;
    const int bb = arow & 63;
    const int tsrc = dir ? (Tz - 1 - tt) : tt;
    const float* aptr = x + ((size_t)bb * Tz + tsrc) * Dz + lk;
    const float* bptr = W + (size_t)(col0 + lrow) * Dz + lk;

    const int tx = tid & 15;
    const int ty = tid >> 4;

    ull acc[8][4];
#pragma unroll
    for (int i = 0; i < 8; i++)
#pragma unroll
        for (int p = 0; p < 4; p++) acc[i][p] = 0ull;

    float4 av = *(const float4*)(aptr);
    float4 bv = *(const float4*)(bptr);

    for (int k0 = 0; k0 < Dz; k0 += 8) {
        AsD[lk + 0][lrow] = dup2(av.x); AsD[lk + 1][lrow] = dup2(av.y);
        AsD[lk + 2][lrow] = dup2(av.z); AsD[lk + 3][lrow] = dup2(av.w);
        Bsf[lk + 0][lrow] = bv.x; Bsf[lk + 1][lrow] = bv.y;
        Bsf[lk + 2][lrow] = bv.z; Bsf[lk + 3][lrow] = bv.w;
        __syncthreads();
        if (k0 + 8 < Dz) {
            av = *(const float4*)(aptr + k0 + 8);
            bv = *(const float4*)(bptr + k0 + 8);
        }
        const ull* bsp = (const ull*)&Bsf[0][0];
#pragma unroll
        for (int kk = 0; kk < 8; kk++) {
            ull a[8], b[4];
#pragma unroll
            for (int i = 0; i < 4; i++) {
                a[i]     = AsD[kk][ty * 4 + i];
                a[4 + i] = AsD[kk][64 + ty * 4 + i];
            }
            b[0] = bsp[kk * 66 + tx * 2 + 0];
            b[1] = bsp[kk * 66 + tx * 2 + 1];
            b[2] = bsp[kk * 66 + 32 + tx * 2 + 0];
            b[3] = bsp[kk * 66 + 32 + tx * 2 + 1];
#pragma unroll
            for (int i = 0; i < 8; i++)
#pragma unroll
                for (int p = 0; p < 4; p++)
                    ffma2(acc[i][p], a[i], b[p]);
        }
        __syncthreads();
    }

    float* outbase = g_gih + (size_t)dir * (Tz * Bz) * Gz;
#pragma unroll
    for (int i = 0; i < 8; i++) {
        int r = row0 + ((i < 4) ? (ty * 4 + i) : (64 + ty * 4 + i - 4));
        float* orow = outbase + (size_t)r * Gz;
#pragma unroll
        for (int p = 0; p < 4; p++) {
            int c = col0 + ((p < 2) ? (tx * 4 + p * 2) : (64 + tx * 4 + (p - 2) * 2));
            union { ull u; float2 f; } cv; cv.u = acc[i][p];
            orow[c + 0] = cv.f.x + bias[c + 0];
            orow[c + 1] = cv.f.y + bias[c + 1];
        }
    }
}

// ---------------- LayerNorm over 4096 (in place) ----------------
__global__ void ln_ih_kernel(const float* __restrict__ gain_f, const float* __restrict__ beta_f,
                             const float* __restrict__ gain_b, const float* __restrict__ beta_b) {
    const int row = blockIdx.x;
    const int dir = row >> 15;
    const float* __restrict__ gain = dir ? gain_b : gain_f;
    const float* __restrict__ beta = dir ? beta_b : beta_f;
    float* p = g_gih + (size_t)row * Gz;
    const int tid = threadIdx.x;

    float4 v[4];
    float sum = 0.f, sq = 0.f;
#pragma unroll
    for (int g = 0; g < 4; g++) {
        v[g] = *(const float4*)(p + g * 1024 + tid * 4);
        sum += v[g].x + v[g].y + v[g].z + v[g].w;
        sq  += v[g].x * v[g].x + v[g].y * v[g].y + v[g].z * v[g].z + v[g].w * v[g].w;
    }
    __shared__ float red[512];
    red[tid] = sum; red[256 + tid] = sq;
    __syncthreads();
    for (int s = 128; s > 0; s >>= 1) {
        if (tid < s) { red[tid] += red[tid + s]; red[256 + tid] += red[256 + tid + s]; }
        __syncthreads();
    }
    float mu = red[0] * (1.f / Gz);
    float var = red[256] * (1.f / Gz) - mu * mu;
    float sc = rsqrtf(var + EPSz);
#pragma unroll
    for (int g = 0; g < 4; g++) {
        int c = g * 1024 + tid * 4;
        float4 gv = *(const float4*)(gain + c);
        float4 bvv = *(const float4*)(beta + c);
        float4 o;
        o.x = (v[g].x - mu) * sc * gv.x + bvv.x;
        o.y = (v[g].y - mu) * sc * gv.y + bvv.y;
        o.z = (v[g].z - mu) * sc * gv.z + bvv.z;
        o.w = (v[g].w - mu) * sc * gv.w + bvv.w;
        *(float4*)(p + c) = o;
    }
}

// h A-fragment write: element (b=row, k) of dir -> (word index, half)
__device__ __forceinline__ void hfrag_addr(int dir, int b, int k, size_t& widx) {
    int kstep = k >> 4;
    int pk = (k >> 1) & 7;
    int r16 = b & 15;
    int mt = b >> 4;
    int T = (r16 & 7) * 4 + (pk & 3);
    int q = (pk >= 4 ? 2 : 0) + (r16 >= 8 ? 1 : 0);
    widx = ((size_t)(dir * 64 + kstep) * 4 + mt) * 128 + T * 4 + q;
}

// ---------------- persistent recurrence: HMMA bf16-split ----------------
// Phase A: CTA (dir, nt, ks): C[64 batch][128 cols] over K=512, 8 warps x n16, 4 m-tiles.
// Phase B: CTA (dir, b): sum 2 partials + LN + cell; write h as A-fragment hi/lo.
__global__ __launch_bounds__(256, 1)
void lstm_persistent(const float* __restrict__ bhh_f, const float* __restrict__ ghh_f,
                     const float* __restrict__ behh_f,
                     const float* __restrict__ bhh_b, const float* __restrict__ ghh_b,
                     const float* __restrict__ behh_b,
                     const float* __restrict__ fwd_init, const float* __restrict__ bwd_init,
                     float* __restrict__ out) {
    __shared__ float red[512];
    const int tid = threadIdx.x;
    const int bid = blockIdx.x;
    const int wrp = tid >> 5;
    const int lane = tid & 31;

    // ---- init h0/c0 (h into fragment images) ----
    for (int i = bid * 256 + tid; i < 2 * Bz * Hz; i += NCTA * 256) {
        int dir0 = i >> 16;
        int b = (i >> 10) & 63;
        int k = i & 1023;
        const float* init = dir0 ? bwd_init : fwd_init;
        float hv = init[k];
        g_c[(size_t)(dir0 * Bz + b) * Hz + k] = init[Hz + k];
        __nv_bfloat16 hh, hl;
        split_bf16(hv, hh, hl);
        size_t widx;
        hfrag_addr(dir0, b, k, widx);
        int half = k & 1;
        ((__nv_bfloat16*)&g_hfh[widx])[half] = hh;
        ((__nv_bfloat16*)&g_hfl[widx])[half] = hl;
    }

    // ---- phase A identifiers ----
    const int dirA = bid >> 6;
    const int nt   = (bid & 63) >> 1;
    const int ks   = bid & 1;
    const int wn   = nt * 8 + wrp;           // global n16-tile index (col = wn*16)
    const uint4* pbh = (const uint4*)g_wfh + ((size_t)(dirA * 256 + wn) * 64 + ks * 32) * 32 + lane;
    const uint4* pbl = (const uint4*)g_wfl + ((size_t)(dirA * 256 + wn) * 64 + ks * 32) * 32 + lane;
    const uint4* pah = (const uint4*)g_hfh + (size_t)(dirA * 64 + ks * 32) * 128 + lane;
    const uint4* pal = (const uint4*)g_hfl + (size_t)(dirA * 64 + ks * 32) * 128 + lane;

    // ---- phase B identifiers ----
    const int dirB = bid >> 6;
    const int cb   = bid & 63;
    const float* __restrict__ bhh  = dirB ? bhh_b  : bhh_f;
    const float* __restrict__ ghh  = dirB ? ghh_b  : ghh_f;
    const float* __restrict__ behh = dirB ? behh_b : behh_f;
    float* cptr = g_c + ((size_t)dirB * Bz + cb) * Hz + tid * 4;
    float* o2   = out + (size_t)Bz * Tz * 2 * Hz + (size_t)cb * (2 * Hz) + dirB * Hz + tid * 4;
    // h-fragment write targets for this thread (k0 = tid*4)
    const int kstepB = tid >> 2;
    const int pk0 = (tid & 3) * 2;
    const int r16B = cb & 15;
    const int mtB = cb >> 4;
    const size_t hbaseB = ((size_t)(dirB * 64 + kstepB) * 4 + mtB) * 128;
    const int T0 = (r16B & 7) * 4 + (pk0 & 3);
    const int T1 = (r16B & 7) * 4 + ((pk0 + 1) & 3);
    const int q0 = (pk0 >= 4 ? 2 : 0) + (r16B >= 8 ? 1 : 0);
    const int q1 = ((pk0 + 1) >= 4 ? 2 : 0) + (r16B >= 8 ? 1 : 0);

    gbar();   // init visible

    for (int t = 0; t < Tz; t++) {
        // ================= phase A: HMMA GEMM =================
        float acc[4][2][4];
#pragma unroll
        for (int m = 0; m < 4; m++)
#pragma unroll
            for (int n = 0; n < 2; n++)
#pragma unroll
                for (int j = 0; j < 4; j++) acc[m][n][j] = 0.f;

        uint4 cah[4], cal[4], cbh, cbl;
        uint4 nah[4], nal[4], nbh, nbl;
#pragma unroll
        for (int m = 0; m < 4; m++) { cah[m] = pah[m * 32]; cal[m] = pal[m * 32]; }
        cbh = pbh[0]; cbl = pbl[0];

        for (int kk = 0; kk < 32; kk++) {
            if (kk < 31) {
                const uint4* ah = pah + (size_t)(kk + 1) * 128;
                const uint4* al = pal + (size_t)(kk + 1) * 128;
#pragma unroll
                for (int m = 0; m < 4; m++) { nah[m] = ah[m * 32]; nal[m] = al[m * 32]; }
                nbh = pbh[(size_t)(kk + 1) * 32];
                nbl = pbl[(size_t)(kk + 1) * 32];
            }
#pragma unroll
            for (int m = 0; m < 4; m++) {
                mma16816(acc[m][0], cah[m], cbh.x, cbh.y);
                mma16816(acc[m][0], cal[m], cbh.x, cbh.y);
                mma16816(acc[m][0], cah[m], cbl.x, cbl.y);
                mma16816(acc[m][1], cah[m], cbh.z, cbh.w);
                mma16816(acc[m][1], cal[m], cbh.z, cbh.w);
                mma16816(acc[m][1], cah[m], cbl.z, cbl.w);
            }
#pragma unroll
            for (int m = 0; m < 4; m++) { cah[m] = nah[m]; cal[m] = nal[m]; }
            cbh = nbh; cbl = nbl;
        }

        // epilogue: write C fragments to g_part [ks][dir][b][col]
        {
            const int r0 = lane >> 2;
            const int cc = wn * 16 + (lane & 3) * 2;
            float* pb = g_part + (size_t)(ks * 2 + dirA) * Bz * Gz;
#pragma unroll
            for (int m = 0; m < 4; m++) {
#pragma unroll
                for (int n = 0; n < 2; n++) {
                    int col = cc + n * 8;
                    *(float2*)&pb[(size_t)(m * 16 + r0) * Gz + col] =
                        make_float2(acc[m][n][0], acc[m][n][1]);
                    *(float2*)&pb[(size_t)(m * 16 + r0 + 8) * Gz + col] =
                        make_float2(acc[m][n][2], acc[m][n][3]);
                }
            }
        }

        gbar();   // partial tiles visible

        // ================= phase B: sum partials + LN + cell =================
        {
            float4 raw[4];
            float sum = 0.f, sq = 0.f;
#pragma unroll
            for (int g = 0; g < 4; g++) {
                int c = g * 1024 + tid * 4;
                float4 p0 = *(const float4*)(g_part + ((size_t)(0 * 2 + dirB) * Bz + cb) * Gz + c);
                float4 p1 = *(const float4*)(g_part + ((size_t)(1 * 2 + dirB) * Bz + cb) * Gz + c);
                float4 bh = *(const float4*)(bhh + c);
                float4 r;
                r.x = p0.x + p1.x + bh.x;
                r.y = p0.y + p1.y + bh.y;
                r.z = p0.z + p1.z + bh.z;
                r.w = p0.w + p1.w + bh.w;
                raw[g] = r;
                sum += r.x + r.y + r.z + r.w;
                sq  += r.x * r.x + r.y * r.y + r.z * r.z + r.w * r.w;
            }
            red[tid] = sum; red[256 + tid] = sq;
            __syncthreads();
            for (int s = 128; s > 0; s >>= 1) {
                if (tid < s) { red[tid] += red[tid + s]; red[256 + tid] += red[256 + tid + s]; }
                __syncthreads();
            }
            float mu = red[0] * (1.f / Gz);
            float var = red[256] * (1.f / Gz) - mu * mu;
            float sc = rsqrtf(var + EPSz);

            const float* gih = g_gih + ((size_t)dirB * Tz * Bz + (size_t)t * Bz + cb) * Gz;
            float gate[4][4];
#pragma unroll
            for (int g = 0; g < 4; g++) {
                int c = g * 1024 + tid * 4;
                float4 gi = *(const float4*)(gih + c);
                float4 gg = *(const float4*)(ghh + c);
                float4 be = *(const float4*)(behh + c);
                gate[g][0] = gi.x + (raw[g].x - mu) * sc * gg.x + be.x;
                gate[g][1] = gi.y + (raw[g].y - mu) * sc * gg.y + be.y;
                gate[g][2] = gi.z + (raw[g].z - mu) * sc * gg.z + be.z;
                gate[g][3] = gi.w + (raw[g].w - mu) * sc * gg.w + be.w;
            }
            float* optr = out + ((size_t)cb * Tz + t) * (2 * Hz) + dirB * Hz + tid * 4;
            float hn4[4];
#pragma unroll
            for (int q = 0; q < 4; q++) {
                float iv = 1.f / (1.f + expf(-gate[0][q]));
                float fv = 1.f / (1.f + expf(-gate[1][q]));
                float gv = tanhf(gate[2][q]);
                float ov = 1.f / (1.f + expf(-gate[3][q]));
                float cn = fv * cptr[q] + iv * gv;
                float hn = ov * tanhf(cn);
                cptr[q] = cn;
                hn4[q] = hn;
                optr[q] = hn;
                if (t == Tz - 1) o2[q] = hn;
            }
            // write h hi/lo fragment words for next step's A operand
            __nv_bfloat16 h0, l0, h1, l1, h2, l2, h3, l3;
            split_bf16(hn4[0], h0, l0);
            split_bf16(hn4[1], h1, l1);
            split_bf16(hn4[2], h2, l2);
            split_bf16(hn4[3], h3, l3);
            g_hfh[hbaseB + T0 * 4 + q0] = pack2(h0, h1);
            g_hfl[hbaseB + T0 * 4 + q0] = pack2(l0, l1);
            g_hfh[hbaseB + T1 * 4 + q1] = pack2(h2, h3);
            g_hfl[hbaseB + T1 * 4 + q1] = pack2(l2, l3);
        }

        gbar();   // new h visible
    }
}

// ---------------- launch ----------------
extern "C" void kernel_launch(void* const* d_in, const int* in_sizes, int n_in,
                              void* d_out, int out_size) {
    const float* x      = (const float*)d_in[0];
    const float* wih_f  = (const float*)d_in[1];
    const float* whh_f  = (const float*)d_in[2];
    const float* bih_f  = (const float*)d_in[3];
    const float* bhh_f  = (const float*)d_in[4];
    const float* gih_f  = (const float*)d_in[5];
    const float* beih_f = (const float*)d_in[6];
    const float* ghh_f  = (const float*)d_in[7];
    const float* behh_f = (const float*)d_in[8];
    const float* wih_b  = (const float*)d_in[9];
    const float* whh_b  = (const float*)d_in[10];
    const float* bih_b  = (const float*)d_in[11];
    const float* bhh_b  = (const float*)d_in[12];
    const float* gih_b  = (const float*)d_in[13];
    const float* beih_b = (const float*)d_in[14];
    const float* ghh_b  = (const float*)d_in[15];
    const float* behh_b = (const float*)d_in[16];
    const float* fwd_init = (const float*)d_in[17];
    const float* bwd_init = (const float*)d_in[18];
    float* out = (float*)d_out;

    prep_w_kernel<<<4096, 256>>>(whh_f, whh_b);
    gemm_ih_kernel<<<dim3(32, 256, 2), 256>>>(x, wih_f, bih_f, wih_b, bih_b);
    ln_ih_kernel<<<65536, 256>>>(gih_f, beih_f, gih_b, beih_b);
    lstm_persistent<<<NCTA, 256>>>(bhh_f, ghh_f, behh_f,
                                   bhh_b, ghh_b, behh_b,
                                   fwd_init, bwd_init, out);
}

// round 8
// speedup vs baseline: 3.4966x; 1.4920x over previous
#include <cuda_runtime.h>
#include <cuda_bf16.h>
#include <math.h>
#include <stdint.h>

#define Bz 64
#define Tz 512
#define Dz 1024
#define Hz 1024
#define Gz 4096          // 4*H
#define EPSz 1e-5f
#define NCTA 128

typedef unsigned long long ull;

// ---------------- scratch (device globals; no runtime allocation) ----------------
__device__ float g_gih[(size_t)2 * Tz * Bz * Gz];      // LN'd input gates [dir][t][b][4H]
// W_hh fragment images: [dir][wn 0..255][kstep 0..63][128 words]
__device__ __align__(16) unsigned g_wfh[(size_t)2 * 256 * 64 * 128];
__device__ __align__(16) unsigned g_wfl[(size_t)2 * 256 * 64 * 128];
// W_ih fragment images (same shape: [4096][1024])
__device__ __align__(16) unsigned g_wihfh[(size_t)2 * 256 * 64 * 128];
__device__ __align__(16) unsigned g_wihfl[(size_t)2 * 256 * 64 * 128];
// x A-fragment images: [t 0..511][kstep 0..63][mt 0..3][128 words]  (64 MB each)
__device__ __align__(16) unsigned g_xfh[(size_t)512 * 64 * 4 * 128];
__device__ __align__(16) unsigned g_xfl[(size_t)512 * 64 * 4 * 128];
// h A-fragment images: [dir][kstep 0..63][mt 0..3][128 words]
__device__ __align__(16) unsigned g_hfh[2 * 64 * 4 * 128];
__device__ __align__(16) unsigned g_hfl[2 * 64 * 4 * 128];
__device__ float g_part[2 * 2 * Bz * Gz];              // [ks][dir][b][4H]
__device__ float g_c[2 * Bz * Hz];                     // cell state
__device__ unsigned g_cnt = 0;
__device__ unsigned g_gen = 0;

// ---------------- helpers ----------------
__device__ __forceinline__ void split_bf16(float v, __nv_bfloat16& hi, __nv_bfloat16& lo) {
    hi = __float2bfloat16(v);
    lo = __float2bfloat16(v - __bfloat162float(hi));
}
__device__ __forceinline__ unsigned pack2(__nv_bfloat16 a, __nv_bfloat16 b) {
    return (unsigned)__bfloat16_as_ushort(a) | ((unsigned)__bfloat16_as_ushort(b) << 16);
}

// HMMA m16n8k16 bf16 row.col, f32 accumulate
__device__ __forceinline__ void mma16816(float* c, const uint4& a, unsigned b0, unsigned b1) {
    asm volatile(
        "mma.sync.aligned.m16n8k16.row.col.f32.bf16.bf16.f32 "
        "{%0,%1,%2,%3}, {%4,%5,%6,%7}, {%8,%9}, {%0,%1,%2,%3};"
        : "+f"(c[0]), "+f"(c[1]), "+f"(c[2]), "+f"(c[3])
        : "r"(a.x), "r"(a.y), "r"(a.z), "r"(a.w), "r"(b0), "r"(b1));
}

// grid-wide barrier (sense-reversing), all NCTA CTAs co-resident
__device__ __forceinline__ void gbar() {
    __syncthreads();
    if (threadIdx.x == 0) {
        unsigned gen = *(volatile unsigned*)&g_gen;
        __threadfence();
        unsigned old = atomicAdd(&g_cnt, 1u);
        if (old == NCTA - 1) {
            atomicExch(&g_cnt, 0u);
            __threadfence();
            atomicAdd(&g_gen, 1u);
        } else {
            while (*(volatile unsigned*)&g_gen == gen) __nanosleep(32);
        }
        __threadfence();
    }
    __syncthreads();
}

// ---------------- prep: weight [4096][1024] -> bf16 hi/lo B-fragment images ----------------
// sel = 0: W_hh -> g_wfh/g_wfl ; sel = 1: W_ih -> g_wihfh/g_wihfl
// (device symbols resolved IN DEVICE CODE — passing them as host-side args is the R7 bug)
__global__ void prep_wfrag_kernel(const float* __restrict__ w_f, const float* __restrict__ w_b,
                                  int sel) {
    unsigned* __restrict__ outh = sel ? g_wihfh : g_wfh;
    unsigned* __restrict__ outl = sel ? g_wihfl : g_wfl;
    int gid = blockIdx.x * 256 + threadIdx.x;     // 2*256*64*32 = 1,048,576
    int T     = gid & 31;
    int kstep = (gid >> 5) & 63;
    int wn    = (gid >> 11) & 255;
    int dir   = gid >> 19;
    const float* __restrict__ W = dir ? w_b : w_f;
    unsigned hw[4], lw[4];
#pragma unroll
    for (int q = 0; q < 4; q++) {
        int c = wn * 16 + (q >> 1) * 8 + (T >> 2);
        int k = kstep * 16 + ((q & 1) * 4 + (T & 3)) * 2;
        float2 v = *(const float2*)(W + (size_t)c * Hz + k);
        __nv_bfloat16 h0, l0, h1, l1;
        split_bf16(v.x, h0, l0);
        split_bf16(v.y, h1, l1);
        hw[q] = pack2(h0, h1);
        lw[q] = pack2(l0, l1);
    }
    size_t base = ((size_t)(dir * 256 + wn) * 64 + kstep) * 128 + T * 4;
    *(uint4*)&outh[base] = make_uint4(hw[0], hw[1], hw[2], hw[3]);
    *(uint4*)&outl[base] = make_uint4(lw[0], lw[1], lw[2], lw[3]);
}

// ---------------- prep: x -> bf16 hi/lo A-fragment images ----------------
__global__ void prep_x_kernel(const float* __restrict__ x) {
    int gid = blockIdx.x * 256 + threadIdx.x;   // 512*64*512 = 16,777,216
    int kw = gid & 511;            // k-pair index (k = kw*2)
    int b  = (gid >> 9) & 63;
    int t  = gid >> 15;
    float2 v = *(const float2*)(x + ((size_t)b * Tz + t) * Dz + kw * 2);
    __nv_bfloat16 h0, l0, h1, l1;
    split_bf16(v.x, h0, l0);
    split_bf16(v.y, h1, l1);
    int kstep = kw >> 3;
    int pk = kw & 7;
    int r16 = b & 15;
    int mt = b >> 4;
    int T = (r16 & 7) * 4 + (pk & 3);
    int q = (pk >= 4 ? 2 : 0) + (r16 >= 8 ? 1 : 0);
    size_t widx = ((size_t)(t * 64 + kstep) * 4 + mt) * 128 + T * 4 + q;
    g_xfh[widx] = pack2(h0, h1);
    g_xfl[widx] = pack2(l0, l1);
}

// ---------------- input-side GEMM: HMMA bf16-split ----------------
// Grid: x = dir*32 + ntile (64), y = mtile (256). CTA tile: M=128 rows, N=128 cols, K=1024.
__global__ __launch_bounds__(256)
void gemm_ih_hmma(const float* __restrict__ bias_f, const float* __restrict__ bias_b) {
    __shared__ uint4 As[2][512];
    __shared__ uint4 Al[2][512];
    const int tid = threadIdx.x;
    const int lane = tid & 31;
    const int wrp = tid >> 5;
    const int dir = blockIdx.x >> 5;
    const int ntile = blockIdx.x & 31;
    const int mtile = blockIdx.y;
    const int wm = wrp >> 2;
    const int wn4 = wrp & 3;
    const float* __restrict__ bias = dir ? bias_b : bias_f;

    const int wn0 = ntile * 8 + wn4 * 2;
    const uint4* pb0h = (const uint4*)g_wihfh + ((size_t)(dir * 256 + wn0) * 64) * 32 + lane;
    const uint4* pb0l = (const uint4*)g_wihfl + ((size_t)(dir * 256 + wn0) * 64) * 32 + lane;
    const uint4* pb1h = (const uint4*)g_wihfh + ((size_t)(dir * 256 + wn0 + 1) * 64) * 32 + lane;
    const uint4* pb1l = (const uint4*)g_wihfl + ((size_t)(dir * 256 + wn0 + 1) * 64) * 32 + lane;

    const uint4* gxh = (const uint4*)g_xfh;
    const uint4* gxl = (const uint4*)g_xfl;

    // A global address (uint4 units) for copy unit u (0..511) of chunk c (2 ksteps)
    auto gaddrA = [&](int c, int u) -> size_t {
        int block = u >> 5;            // 0..15 = ks2*8 + mtg
        int ks2 = block >> 3;
        int mtg = block & 7;
        int l4 = u & 31;
        int v = mtile * 2 + (mtg >> 2);
        int t = dir ? (511 - v) : v;
        return ((size_t)(t * 64 + c * 2 + ks2) * 4 + (mtg & 3)) * 32 + l4;
    };

    float acc[4][4][4];
#pragma unroll
    for (int i = 0; i < 4; i++)
#pragma unroll
        for (int n = 0; n < 4; n++)
#pragma unroll
            for (int j = 0; j < 4; j++) acc[i][n][j] = 0.f;

    // stage chunk 0
    As[0][tid] = gxh[gaddrA(0, tid)];
    As[0][tid + 256] = gxh[gaddrA(0, tid + 256)];
    Al[0][tid] = gxl[gaddrA(0, tid)];
    Al[0][tid + 256] = gxl[gaddrA(0, tid + 256)];
    __syncthreads();

    uint4 cb0h = pb0h[0], cb0l = pb0l[0], cb1h = pb1h[0], cb1l = pb1l[0];

    for (int c = 0; c < 32; c++) {
        const int cur = c & 1;
        uint4 rh0, rh1, rl0, rl1;
        if (c < 31) {
            rh0 = gxh[gaddrA(c + 1, tid)];
            rh1 = gxh[gaddrA(c + 1, tid + 256)];
            rl0 = gxl[gaddrA(c + 1, tid)];
            rl1 = gxl[gaddrA(c + 1, tid + 256)];
        }
#pragma unroll
        for (int ks2 = 0; ks2 < 2; ks2++) {
            const int kstep = c * 2 + ks2;
            uint4 nb0h = cb0h, nb0l = cb0l, nb1h = cb1h, nb1l = cb1l;
            if (kstep < 63) {
                size_t o = (size_t)(kstep + 1) * 32;
                nb0h = pb0h[o]; nb0l = pb0l[o];
                nb1h = pb1h[o]; nb1l = pb1l[o];
            }
            uint4 ah[4], al[4];
#pragma unroll
            for (int i = 0; i < 4; i++) {
                int sb = (ks2 * 8 + wm * 4 + i) * 32 + lane;
                ah[i] = As[cur][sb];
                al[i] = Al[cur][sb];
            }
#pragma unroll
            for (int i = 0; i < 4; i++) {
                mma16816(acc[i][0], ah[i], cb0h.x, cb0h.y);
                mma16816(acc[i][0], al[i], cb0h.x, cb0h.y);
                mma16816(acc[i][0], ah[i], cb0l.x, cb0l.y);
                mma16816(acc[i][1], ah[i], cb0h.z, cb0h.w);
                mma16816(acc[i][1], al[i], cb0h.z, cb0h.w);
                mma16816(acc[i][1], ah[i], cb0l.z, cb0l.w);
                mma16816(acc[i][2], ah[i], cb1h.x, cb1h.y);
                mma16816(acc[i][2], al[i], cb1h.x, cb1h.y);
                mma16816(acc[i][2], ah[i], cb1l.x, cb1l.y);
                mma16816(acc[i][3], ah[i], cb1h.z, cb1h.w);
                mma16816(acc[i][3], al[i], cb1h.z, cb1h.w);
                mma16816(acc[i][3], ah[i], cb1l.z, cb1l.w);
            }
            cb0h = nb0h; cb0l = nb0l; cb1h = nb1h; cb1l = nb1l;
        }
        if (c < 31) {
            const int nxt = cur ^ 1;
            As[nxt][tid] = rh0; As[nxt][tid + 256] = rh1;
            Al[nxt][tid] = rl0; Al[nxt][tid + 256] = rl1;
            __syncthreads();
        }
    }

    // epilogue: fragments + bias -> g_gih
    const int r0 = lane >> 2;
    const int cp = (lane & 3) * 2;
    float* outbase = g_gih + (size_t)dir * (Tz * Bz) * Gz;
#pragma unroll
    for (int i = 0; i < 4; i++) {
        const int mtg = wm * 4 + i;
        const int rbase = mtile * 128 + (mtg >> 2) * 64 + (mtg & 3) * 16;
#pragma unroll
        for (int n8 = 0; n8 < 4; n8++) {
            const int col = ntile * 128 + wn4 * 32 + n8 * 8 + cp;
            float2 bv = *(const float2*)(bias + col);
            float* d0 = outbase + (size_t)(rbase + r0) * Gz + col;
            float* d1 = outbase + (size_t)(rbase + r0 + 8) * Gz + col;
            *(float2*)d0 = make_float2(acc[i][n8][0] + bv.x, acc[i][n8][1] + bv.y);
            *(float2*)d1 = make_float2(acc[i][n8][2] + bv.x, acc[i][n8][3] + bv.y);
        }
    }
}

// ---------------- LayerNorm over 4096 (in place) ----------------
__global__ void ln_ih_kernel(const float* __restrict__ gain_f, const float* __restrict__ beta_f,
                             const float* __restrict__ gain_b, const float* __restrict__ beta_b) {
    const int row = blockIdx.x;
    const int dir = row >> 15;
    const float* __restrict__ gain = dir ? gain_b : gain_f;
    const float* __restrict__ beta = dir ? beta_b : beta_f;
    float* p = g_gih + (size_t)row * Gz;
    const int tid = threadIdx.x;

    float4 v[4];
    float sum = 0.f, sq = 0.f;
#pragma unroll
    for (int g = 0; g < 4; g++) {
        v[g] = *(const float4*)(p + g * 1024 + tid * 4);
        sum += v[g].x + v[g].y + v[g].z + v[g].w;
        sq  += v[g].x * v[g].x + v[g].y * v[g].y + v[g].z * v[g].z + v[g].w * v[g].w;
    }
    __shared__ float red[512];
    red[tid] = sum; red[256 + tid] = sq;
    __syncthreads();
    for (int s = 128; s > 0; s >>= 1) {
        if (tid < s) { red[tid] += red[tid + s]; red[256 + tid] += red[256 + tid + s]; }
        __syncthreads();
    }
    float mu = red[0] * (1.f / Gz);
    float var = red[256] * (1.f / Gz) - mu * mu;
    float sc = rsqrtf(var + EPSz);
#pragma unroll
    for (int g = 0; g < 4; g++) {
        int c = g * 1024 + tid * 4;
        float4 gv = *(const float4*)(gain + c);
        float4 bvv = *(const float4*)(beta + c);
        float4 o;
        o.x = (v[g].x - mu) * sc * gv.x + bvv.x;
        o.y = (v[g].y - mu) * sc * gv.y + bvv.y;
        o.z = (v[g].z - mu) * sc * gv.z + bvv.z;
        o.w = (v[g].w - mu) * sc * gv.w + bvv.w;
        *(float4*)(p + c) = o;
    }
}

// h A-fragment write: element (b=row, k) of dir -> word index
__device__ __forceinline__ void hfrag_addr(int dir, int b, int k, size_t& widx) {
    int kstep = k >> 4;
    int pk = (k >> 1) & 7;
    int r16 = b & 15;
    int mt = b >> 4;
    int T = (r16 & 7) * 4 + (pk & 3);
    int q = (pk >= 4 ? 2 : 0) + (r16 >= 8 ? 1 : 0);
    widx = ((size_t)(dir * 64 + kstep) * 4 + mt) * 128 + T * 4 + q;
}

// ---------------- persistent recurrence: HMMA bf16-split (unchanged from R6) ----------------
__global__ __launch_bounds__(256, 1)
void lstm_persistent(const float* __restrict__ bhh_f, const float* __restrict__ ghh_f,
                     const float* __restrict__ behh_f,
                     const float* __restrict__ bhh_b, const float* __restrict__ ghh_b,
                     const float* __restrict__ behh_b,
                     const float* __restrict__ fwd_init, const float* __restrict__ bwd_init,
                     float* __restrict__ out) {
    __shared__ float red[512];
    const int tid = threadIdx.x;
    const int bid = blockIdx.x;
    const int wrp = tid >> 5;
    const int lane = tid & 31;

    // ---- init h0/c0 (h into fragment images) ----
    for (int i = bid * 256 + tid; i < 2 * Bz * Hz; i += NCTA * 256) {
        int dir0 = i >> 16;
        int b = (i >> 10) & 63;
        int k = i & 1023;
        const float* init = dir0 ? bwd_init : fwd_init;
        float hv = init[k];
        g_c[(size_t)(dir0 * Bz + b) * Hz + k] = init[Hz + k];
        __nv_bfloat16 hh, hl;
        split_bf16(hv, hh, hl);
        size_t widx;
        hfrag_addr(dir0, b, k, widx);
        int half = k & 1;
        ((__nv_bfloat16*)&g_hfh[widx])[half] = hh;
        ((__nv_bfloat16*)&g_hfl[widx])[half] = hl;
    }

    // ---- phase A identifiers ----
    const int dirA = bid >> 6;
    const int nt   = (bid & 63) >> 1;
    const int ks   = bid & 1;
    const int wn   = nt * 8 + wrp;
    const uint4* pbh = (const uint4*)g_wfh + ((size_t)(dirA * 256 + wn) * 64 + ks * 32) * 32 + lane;
    const uint4* pbl = (const uint4*)g_wfl + ((size_t)(dirA * 256 + wn) * 64 + ks * 32) * 32 + lane;
    const uint4* pah = (const uint4*)g_hfh + (size_t)(dirA * 64 + ks * 32) * 128 + lane;
    const uint4* pal = (const uint4*)g_hfl + (size_t)(dirA * 64 + ks * 32) * 128 + lane;

    // ---- phase B identifiers ----
    const int dirB = bid >> 6;
    const int cb   = bid & 63;
    const float* __restrict__ bhh  = dirB ? bhh_b  : bhh_f;
    const float* __restrict__ ghh  = dirB ? ghh_b  : ghh_f;
    const float* __restrict__ behh = dirB ? behh_b : behh_f;
    float* cptr = g_c + ((size_t)dirB * Bz + cb) * Hz + tid * 4;
    float* o2   = out + (size_t)Bz * Tz * 2 * Hz + (size_t)cb * (2 * Hz) + dirB * Hz + tid * 4;
    const int kstepB = tid >> 2;
    const int pk0 = (tid & 3) * 2;
    const int r16B = cb & 15;
    const int mtB = cb >> 4;
    const size_t hbaseB = ((size_t)(dirB * 64 + kstepB) * 4 + mtB) * 128;
    const int T0 = (r16B & 7) * 4 + (pk0 & 3);
    const int T1 = (r16B & 7) * 4 + ((pk0 + 1) & 3);
    const int q0 = (pk0 >= 4 ? 2 : 0) + (r16B >= 8 ? 1 : 0);
    const int q1 = ((pk0 + 1) >= 4 ? 2 : 0) + (r16B >= 8 ? 1 : 0);

    gbar();   // init visible

    for (int t = 0; t < Tz; t++) {
        // ================= phase A: HMMA GEMM =================
        float acc[4][2][4];
#pragma unroll
        for (int m = 0; m < 4; m++)
#pragma unroll
            for (int n = 0; n < 2; n++)
#pragma unroll
                for (int j = 0; j < 4; j++) acc[m][n][j] = 0.f;

        uint4 cah[4], cal[4], cbh, cbl;
        uint4 nah[4], nal[4], nbh, nbl;
#pragma unroll
        for (int m = 0; m < 4; m++) { cah[m] = pah[m * 32]; cal[m] = pal[m * 32]; }
        cbh = pbh[0]; cbl = pbl[0];

        for (int kk = 0; kk < 32; kk++) {
            if (kk < 31) {
                const uint4* ah = pah + (size_t)(kk + 1) * 128;
                const uint4* al = pal + (size_t)(kk + 1) * 128;
#pragma unroll
                for (int m = 0; m < 4; m++) { nah[m] = ah[m * 32]; nal[m] = al[m * 32]; }
                nbh = pbh[(size_t)(kk + 1) * 32];
                nbl = pbl[(size_t)(kk + 1) * 32];
            }
#pragma unroll
            for (int m = 0; m < 4; m++) {
                mma16816(acc[m][0], cah[m], cbh.x, cbh.y);
                mma16816(acc[m][0], cal[m], cbh.x, cbh.y);
                mma16816(acc[m][0], cah[m], cbl.x, cbl.y);
                mma16816(acc[m][1], cah[m], cbh.z, cbh.w);
                mma16816(acc[m][1], cal[m], cbh.z, cbh.w);
                mma16816(acc[m][1], cah[m], cbl.z, cbl.w);
            }
#pragma unroll
            for (int m = 0; m < 4; m++) { cah[m] = nah[m]; cal[m] = nal[m]; }
            cbh = nbh; cbl = nbl;
        }

        // epilogue: write C fragments to g_part [ks][dir][b][col]
        {
            const int r0 = lane >> 2;
            const int cc = wn * 16 + (lane & 3) * 2;
            float* pb = g_part + (size_t)(ks * 2 + dirA) * Bz * Gz;
#pragma unroll
            for (int m = 0; m < 4; m++) {
#pragma unroll
                for (int n = 0; n < 2; n++) {
                    int col = cc + n * 8;
                    *(float2*)&pb[(size_t)(m * 16 + r0) * Gz + col] =
                        make_float2(acc[m][n][0], acc[m][n][1]);
                    *(float2*)&pb[(size_t)(m * 16 + r0 + 8) * Gz + col] =
                        make_float2(acc[m][n][2], acc[m][n][3]);
                }
            }
        }

        gbar();   // partial tiles visible

        // ================= phase B: sum partials + LN + cell =================
        {
            float4 raw[4];
            float sum = 0.f, sq = 0.f;
#pragma unroll
            for (int g = 0; g < 4; g++) {
                int c = g * 1024 + tid * 4;
                float4 p0 = *(const float4*)(g_part + ((size_t)(0 * 2 + dirB) * Bz + cb) * Gz + c);
                float4 p1 = *(const float4*)(g_part + ((size_t)(1 * 2 + dirB) * Bz + cb) * Gz + c);
                float4 bh = *(const float4*)(bhh + c);
                float4 r;
                r.x = p0.x + p1.x + bh.x;
                r.y = p0.y + p1.y + bh.y;
                r.z = p0.z + p1.z + bh.z;
                r.w = p0.w + p1.w + bh.w;
                raw[g] = r;
                sum += r.x + r.y + r.z + r.w;
                sq  += r.x * r.x + r.y * r.y + r.z * r.z + r.w * r.w;
            }
            red[tid] = sum; red[256 + tid] = sq;
            __syncthreads();
            for (int s = 128; s > 0; s >>= 1) {
                if (tid < s) { red[tid] += red[tid + s]; red[256 + tid] += red[256 + tid + s]; }
                __syncthreads();
            }
            float mu = red[0] * (1.f / Gz);
            float var = red[256] * (1.f / Gz) - mu * mu;
            float sc = rsqrtf(var + EPSz);

            const float* gih = g_gih + ((size_t)dirB * Tz * Bz + (size_t)t * Bz + cb) * Gz;
            float gate[4][4];
#pragma unroll
            for (int g = 0; g < 4; g++) {
                int c = g * 1024 + tid * 4;
                float4 gi = *(const float4*)(gih + c);
                float4 gg = *(const float4*)(ghh + c);
                float4 be = *(const float4*)(behh + c);
                gate[g][0] = gi.x + (raw[g].x - mu) * sc * gg.x + be.x;
                gate[g][1] = gi.y + (raw[g].y - mu) * sc * gg.y + be.y;
                gate[g][2] = gi.z + (raw[g].z - mu) * sc * gg.z + be.z;
                gate[g][3] = gi.w + (raw[g].w - mu) * sc * gg.w + be.w;
            }
            float* optr = out + ((size_t)cb * Tz + t) * (2 * Hz) + dirB * Hz + tid * 4;
            float hn4[4];
#pragma unroll
            for (int q = 0; q < 4; q++) {
                float iv = 1.f / (1.f + expf(-gate[0][q]));
                float fv = 1.f / (1.f + expf(-gate[1][q]));
                float gv = tanhf(gate[2][q]);
                float ov = 1.f / (1.f + expf(-gate[3][q]));
                float cn = fv * cptr[q] + iv * gv;
                float hn = ov * tanhf(cn);
                cptr[q] = cn;
                hn4[q] = hn;
                optr[q] = hn;
                if (t == Tz - 1) o2[q] = hn;
            }
            __nv_bfloat16 h0, l0, h1, l1, h2, l2, h3, l3;
            split_bf16(hn4[0], h0, l0);
            split_bf16(hn4[1], h1, l1);
            split_bf16(hn4[2], h2, l2);
            split_bf16(hn4[3], h3, l3);
            g_hfh[hbaseB + T0 * 4 + q0] = pack2(h0, h1);
            g_hfl[hbaseB + T0 * 4 + q0] = pack2(l0, l1);
            g_hfh[hbaseB + T1 * 4 + q1] = pack2(h2, h3);
            g_hfl[hbaseB + T1 * 4 + q1] = pack2(l2, l3);
        }

        gbar();   // new h visible
    }
}

// ---------------- launch ----------------
extern "C" void kernel_launch(void* const* d_in, const int* in_sizes, int n_in,
                              void* d_out, int out_size) {
    const float* x      = (const float*)d_in[0];
    const float* wih_f  = (const float*)d_in[1];
    const float* whh_f  = (const float*)d_in[2];
    const float* bih_f  = (const float*)d_in[3];
    const float* bhh_f  = (const float*)d_in[4];
    const float* gih_f  = (const float*)d_in[5];
    const float* beih_f = (const float*)d_in[6];
    const float* ghh_f  = (const float*)d_in[7];
    const float* behh_f = (const float*)d_in[8];
    const float* wih_b  = (const float*)d_in[9];
    const float* whh_b  = (const float*)d_in[10];
    const float* bih_b  = (const float*)d_in[11];
    const float* bhh_b  = (const float*)d_in[12];
    const float* gih_b  = (const float*)d_in[13];
    const float* beih_b = (const float*)d_in[14];
    const float* ghh_b  = (const float*)d_in[15];
    const float* behh_b = (const float*)d_in[16];
    const float* fwd_init = (const float*)d_in[17];
    const float* bwd_init = (const float*)d_in[18];
    float* out = (float*)d_out;

    prep_wfrag_kernel<<<4096, 256>>>(whh_f, whh_b, 0);
    prep_wfrag_kernel<<<4096, 256>>>(wih_f, wih_b, 1);
    prep_x_kernel<<<65536, 256>>>(x);
    gemm_ih_hmma<<<dim3(64, 256), 256>>>(bih_f, bih_b);
    ln_ih_kernel<<<65536, 256>>>(gih_f, beih_f, gih_b, beih_b);
    lstm_persistent<<<NCTA, 256>>>(bhh_f, ghh_f, behh_f,
                                   bhh_b, ghh_b, behh_b,
                                   fwd_init, bwd_init, out);
}

// round 9
// speedup vs baseline: 3.9294x; 1.1238x over previous
#include <cuda_runtime.h>
#include <cuda_bf16.h>
#include <math.h>
#include <stdint.h>

#define Bz 64
#define Tz 512
#define Dz 1024
#define Hz 1024
#define Gz 4096          // 4*H
#define EPSz 1e-5f
#define NCTA 128

typedef unsigned long long ull;

// ---------------- scratch (device globals; no runtime allocation) ----------------
__device__ float g_gih[(size_t)2 * Tz * Bz * Gz];      // LN'd input gates [dir][t][b][4H]
// W_hh fragment images: [dir][wn 0..255][kstep 0..63][128 words]
__device__ __align__(16) unsigned g_wfh[(size_t)2 * 256 * 64 * 128];
__device__ __align__(16) unsigned g_wfl[(size_t)2 * 256 * 64 * 128];
// W_ih fragment images (same shape: [4096][1024])
__device__ __align__(16) unsigned g_wihfh[(size_t)2 * 256 * 64 * 128];
__device__ __align__(16) unsigned g_wihfl[(size_t)2 * 256 * 64 * 128];
// x A-fragment images: [t 0..511][kstep 0..63][mt 0..3][128 words]
__device__ __align__(16) unsigned g_xfh[(size_t)512 * 64 * 4 * 128];
__device__ __align__(16) unsigned g_xfl[(size_t)512 * 64 * 4 * 128];
// h A-fragment images: [dir][kstep 0..63][mt 0..3][128 words]
__device__ __align__(16) unsigned g_hfh[2 * 64 * 4 * 128];
__device__ __align__(16) unsigned g_hfl[2 * 64 * 4 * 128];
__device__ float g_part[8 * Bz * Gz];                  // [ks 0..3][dir][b][4H]
__device__ float g_c[2 * Bz * Hz];                     // cell state
__device__ unsigned g_cnt = 0;
__device__ unsigned g_gen = 0;

// ---------------- helpers ----------------
__device__ __forceinline__ void split_bf16(float v, __nv_bfloat16& hi, __nv_bfloat16& lo) {
    hi = __float2bfloat16(v);
    lo = __float2bfloat16(v - __bfloat162float(hi));
}
__device__ __forceinline__ unsigned pack2(__nv_bfloat16 a, __nv_bfloat16 b) {
    return (unsigned)__bfloat16_as_ushort(a) | ((unsigned)__bfloat16_as_ushort(b) << 16);
}

// HMMA m16n8k16 bf16 row.col, f32 accumulate
__device__ __forceinline__ void mma16816(float* c, const uint4& a, unsigned b0, unsigned b1) {
    asm volatile(
        "mma.sync.aligned.m16n8k16.row.col.f32.bf16.bf16.f32 "
        "{%0,%1,%2,%3}, {%4,%5,%6,%7}, {%8,%9}, {%0,%1,%2,%3};"
        : "+f"(c[0]), "+f"(c[1]), "+f"(c[2]), "+f"(c[3])
        : "r"(a.x), "r"(a.y), "r"(a.z), "r"(a.w), "r"(b0), "r"(b1));
}

// grid-wide barrier (sense-reversing), all NCTA CTAs co-resident
__device__ __forceinline__ void gbar() {
    __syncthreads();
    if (threadIdx.x == 0) {
        unsigned gen = *(volatile unsigned*)&g_gen;
        __threadfence();
        unsigned old = atomicAdd(&g_cnt, 1u);
        if (old == NCTA - 1) {
            atomicExch(&g_cnt, 0u);
            __threadfence();
            atomicAdd(&g_gen, 1u);
        } else {
            while (*(volatile unsigned*)&g_gen == gen) __nanosleep(32);
        }
        __threadfence();
    }
    __syncthreads();
}

// ---------------- prep: weight [4096][1024] -> bf16 hi/lo B-fragment images ----------------
__global__ void prep_wfrag_kernel(const float* __restrict__ w_f, const float* __restrict__ w_b,
                                  int sel) {
    unsigned* __restrict__ outh = sel ? g_wihfh : g_wfh;
    unsigned* __restrict__ outl = sel ? g_wihfl : g_wfl;
    int gid = blockIdx.x * 256 + threadIdx.x;
    int T     = gid & 31;
    int kstep = (gid >> 5) & 63;
    int wn    = (gid >> 11) & 255;
    int dir   = gid >> 19;
    const float* __restrict__ W = dir ? w_b : w_f;
    unsigned hw[4], lw[4];
#pragma unroll
    for (int q = 0; q < 4; q++) {
        int c = wn * 16 + (q >> 1) * 8 + (T >> 2);
        int k = kstep * 16 + ((q & 1) * 4 + (T & 3)) * 2;
        float2 v = *(const float2*)(W + (size_t)c * Hz + k);
        __nv_bfloat16 h0, l0, h1, l1;
        split_bf16(v.x, h0, l0);
        split_bf16(v.y, h1, l1);
        hw[q] = pack2(h0, h1);
        lw[q] = pack2(l0, l1);
    }
    size_t base = ((size_t)(dir * 256 + wn) * 64 + kstep) * 128 + T * 4;
    *(uint4*)&outh[base] = make_uint4(hw[0], hw[1], hw[2], hw[3]);
    *(uint4*)&outl[base] = make_uint4(lw[0], lw[1], lw[2], lw[3]);
}

// ---------------- prep: x -> bf16 hi/lo A-fragment images ----------------
__global__ void prep_x_kernel(const float* __restrict__ x) {
    int gid = blockIdx.x * 256 + threadIdx.x;
    int kw = gid & 511;
    int b  = (gid >> 9) & 63;
    int t  = gid >> 15;
    float2 v = *(const float2*)(x + ((size_t)b * Tz + t) * Dz + kw * 2);
    __nv_bfloat16 h0, l0, h1, l1;
    split_bf16(v.x, h0, l0);
    split_bf16(v.y, h1, l1);
    int kstep = kw >> 3;
    int pk = kw & 7;
    int r16 = b & 15;
    int mt = b >> 4;
    int T = (r16 & 7) * 4 + (pk & 3);
    int q = (pk >= 4 ? 2 : 0) + (r16 >= 8 ? 1 : 0);
    size_t widx = ((size_t)(t * 64 + kstep) * 4 + mt) * 128 + T * 4 + q;
    g_xfh[widx] = pack2(h0, h1);
    g_xfl[widx] = pack2(l0, l1);
}

// ---------------- input-side GEMM: HMMA bf16-split (unchanged from R8) ----------------
__global__ __launch_bounds__(256)
void gemm_ih_hmma(const float* __restrict__ bias_f, const float* __restrict__ bias_b) {
    __shared__ uint4 As[2][512];
    __shared__ uint4 Al[2][512];
    const int tid = threadIdx.x;
    const int lane = tid & 31;
    const int wrp = tid >> 5;
    const int dir = blockIdx.x >> 5;
    const int ntile = blockIdx.x & 31;
    const int mtile = blockIdx.y;
    const int wm = wrp >> 2;
    const int wn4 = wrp & 3;
    const float* __restrict__ bias = dir ? bias_b : bias_f;

    const int wn0 = ntile * 8 + wn4 * 2;
    const uint4* pb0h = (const uint4*)g_wihfh + ((size_t)(dir * 256 + wn0) * 64) * 32 + lane;
    const uint4* pb0l = (const uint4*)g_wihfl + ((size_t)(dir * 256 + wn0) * 64) * 32 + lane;
    const uint4* pb1h = (const uint4*)g_wihfh + ((size_t)(dir * 256 + wn0 + 1) * 64) * 32 + lane;
    const uint4* pb1l = (const uint4*)g_wihfl + ((size_t)(dir * 256 + wn0 + 1) * 64) * 32 + lane;

    const uint4* gxh = (const uint4*)g_xfh;
    const uint4* gxl = (const uint4*)g_xfl;

    auto gaddrA = [&](int c, int u) -> size_t {
        int block = u >> 5;
        int ks2 = block >> 3;
        int mtg = block & 7;
        int l4 = u & 31;
        int v = mtile * 2 + (mtg >> 2);
        int t = dir ? (511 - v) : v;
        return ((size_t)(t * 64 + c * 2 + ks2) * 4 + (mtg & 3)) * 32 + l4;
    };

    float acc[4][4][4];
#pragma unroll
    for (int i = 0; i < 4; i++)
#pragma unroll
        for (int n = 0; n < 4; n++)
#pragma unroll
            for (int j = 0; j < 4; j++) acc[i][n][j] = 0.f;

    As[0][tid] = gxh[gaddrA(0, tid)];
    As[0][tid + 256] = gxh[gaddrA(0, tid + 256)];
    Al[0][tid] = gxl[gaddrA(0, tid)];
    Al[0][tid + 256] = gxl[gaddrA(0, tid + 256)];
    __syncthreads();

    uint4 cb0h = pb0h[0], cb0l = pb0l[0], cb1h = pb1h[0], cb1l = pb1l[0];

    for (int c = 0; c < 32; c++) {
        const int cur = c & 1;
        uint4 rh0, rh1, rl0, rl1;
        if (c < 31) {
            rh0 = gxh[gaddrA(c + 1, tid)];
            rh1 = gxh[gaddrA(c + 1, tid + 256)];
            rl0 = gxl[gaddrA(c + 1, tid)];
            rl1 = gxl[gaddrA(c + 1, tid + 256)];
        }
#pragma unroll
        for (int ks2 = 0; ks2 < 2; ks2++) {
            const int kstep = c * 2 + ks2;
            uint4 nb0h = cb0h, nb0l = cb0l, nb1h = cb1h, nb1l = cb1l;
            if (kstep < 63) {
                size_t o = (size_t)(kstep + 1) * 32;
                nb0h = pb0h[o]; nb0l = pb0l[o];
                nb1h = pb1h[o]; nb1l = pb1l[o];
            }
            uint4 ah[4], al[4];
#pragma unroll
            for (int i = 0; i < 4; i++) {
                int sb = (ks2 * 8 + wm * 4 + i) * 32 + lane;
                ah[i] = As[cur][sb];
                al[i] = Al[cur][sb];
            }
#pragma unroll
            for (int i = 0; i < 4; i++) {
                mma16816(acc[i][0], ah[i], cb0h.x, cb0h.y);
                mma16816(acc[i][0], al[i], cb0h.x, cb0h.y);
                mma16816(acc[i][0], ah[i], cb0l.x, cb0l.y);
                mma16816(acc[i][1], ah[i], cb0h.z, cb0h.w);
                mma16816(acc[i][1], al[i], cb0h.z, cb0h.w);
                mma16816(acc[i][1], ah[i], cb0l.z, cb0l.w);
                mma16816(acc[i][2], ah[i], cb1h.x, cb1h.y);
                mma16816(acc[i][2], al[i], cb1h.x, cb1h.y);
                mma16816(acc[i][2], ah[i], cb1l.x, cb1l.y);
                mma16816(acc[i][3], ah[i], cb1h.z, cb1h.w);
                mma16816(acc[i][3], al[i], cb1h.z, cb1h.w);
                mma16816(acc[i][3], ah[i], cb1l.z, cb1l.w);
            }
            cb0h = nb0h; cb0l = nb0l; cb1h = nb1h; cb1l = nb1l;
        }
        if (c < 31) {
            const int nxt = cur ^ 1;
            As[nxt][tid] = rh0; As[nxt][tid + 256] = rh1;
            Al[nxt][tid] = rl0; Al[nxt][tid + 256] = rl1;
            __syncthreads();
        }
    }

    const int r0 = lane >> 2;
    const int cp = (lane & 3) * 2;
    float* outbase = g_gih + (size_t)dir * (Tz * Bz) * Gz;
#pragma unroll
    for (int i = 0; i < 4; i++) {
        const int mtg = wm * 4 + i;
        const int rbase = mtile * 128 + (mtg >> 2) * 64 + (mtg & 3) * 16;
#pragma unroll
        for (int n8 = 0; n8 < 4; n8++) {
            const int col = ntile * 128 + wn4 * 32 + n8 * 8 + cp;
            float2 bv = *(const float2*)(bias + col);
            float* d0 = outbase + (size_t)(rbase + r0) * Gz + col;
            float* d1 = outbase + (size_t)(rbase + r0 + 8) * Gz + col;
            *(float2*)d0 = make_float2(acc[i][n8][0] + bv.x, acc[i][n8][1] + bv.y);
            *(float2*)d1 = make_float2(acc[i][n8][2] + bv.x, acc[i][n8][3] + bv.y);
        }
    }
}

// ---------------- LayerNorm over 4096 (in place) ----------------
__global__ void ln_ih_kernel(const float* __restrict__ gain_f, const float* __restrict__ beta_f,
                             const float* __restrict__ gain_b, const float* __restrict__ beta_b) {
    const int row = blockIdx.x;
    const int dir = row >> 15;
    const float* __restrict__ gain = dir ? gain_b : gain_f;
    const float* __restrict__ beta = dir ? beta_b : beta_f;
    float* p = g_gih + (size_t)row * Gz;
    const int tid = threadIdx.x;

    float4 v[4];
    float sum = 0.f, sq = 0.f;
#pragma unroll
    for (int g = 0; g < 4; g++) {
        v[g] = *(const float4*)(p + g * 1024 + tid * 4);
        sum += v[g].x + v[g].y + v[g].z + v[g].w;
        sq  += v[g].x * v[g].x + v[g].y * v[g].y + v[g].z * v[g].z + v[g].w * v[g].w;
    }
    __shared__ float red[512];
    red[tid] = sum; red[256 + tid] = sq;
    __syncthreads();
    for (int s = 128; s > 0; s >>= 1) {
        if (tid < s) { red[tid] += red[tid + s]; red[256 + tid] += red[256 + tid + s]; }
        __syncthreads();
    }
    float mu = red[0] * (1.f / Gz);
    float var = red[256] * (1.f / Gz) - mu * mu;
    float sc = rsqrtf(var + EPSz);
#pragma unroll
    for (int g = 0; g < 4; g++) {
        int c = g * 1024 + tid * 4;
        float4 gv = *(const float4*)(gain + c);
        float4 bvv = *(const float4*)(beta + c);
        float4 o;
        o.x = (v[g].x - mu) * sc * gv.x + bvv.x;
        o.y = (v[g].y - mu) * sc * gv.y + bvv.y;
        o.z = (v[g].z - mu) * sc * gv.z + bvv.z;
        o.w = (v[g].w - mu) * sc * gv.w + bvv.w;
        *(float4*)(p + c) = o;
    }
}

// h A-fragment write: element (b=row, k) of dir -> word index
__device__ __forceinline__ void hfrag_addr(int dir, int b, int k, size_t& widx) {
    int kstep = k >> 4;
    int pk = (k >> 1) & 7;
    int r16 = b & 15;
    int mt = b >> 4;
    int T = (r16 & 7) * 4 + (pk & 3);
    int q = (pk >= 4 ? 2 : 0) + (r16 >= 8 ? 1 : 0);
    widx = ((size_t)(dir * 64 + kstep) * 4 + mt) * 128 + T * 4 + q;
}

// ---------------- persistent recurrence: 512 threads, 16 warps, 4-way K-split ----------------
// Phase A: CTA (dir, nt 0..15, ks 0..3): warps cover 256 cols (16 x n16), K=256 slice.
// Phase B: CTA (dir, b): sum 4 partials + LN + cell (2 elements/thread).
__global__ __launch_bounds__(512, 1)
void lstm_persistent(const float* __restrict__ bhh_f, const float* __restrict__ ghh_f,
                     const float* __restrict__ behh_f,
                     const float* __restrict__ bhh_b, const float* __restrict__ ghh_b,
                     const float* __restrict__ behh_b,
                     const float* __restrict__ fwd_init, const float* __restrict__ bwd_init,
                     float* __restrict__ out) {
    __shared__ float red[1024];
    const int tid = threadIdx.x;
    const int bid = blockIdx.x;
    const int wrp = tid >> 5;
    const int lane = tid & 31;

    // ---- init h0/c0 ----
    for (int i = bid * 512 + tid; i < 2 * Bz * Hz; i += NCTA * 512) {
        int dir0 = i >> 16;
        int b = (i >> 10) & 63;
        int k = i & 1023;
        const float* init = dir0 ? bwd_init : fwd_init;
        float hv = init[k];
        g_c[(size_t)(dir0 * Bz + b) * Hz + k] = init[Hz + k];
        __nv_bfloat16 hh, hl;
        split_bf16(hv, hh, hl);
        size_t widx;
        hfrag_addr(dir0, b, k, widx);
        int half = k & 1;
        ((__nv_bfloat16*)&g_hfh[widx])[half] = hh;
        ((__nv_bfloat16*)&g_hfl[widx])[half] = hl;
    }

    // ---- phase A identifiers: bid = dir*64 + nt*4 + ks ----
    const int dirA = bid >> 6;
    const int nt   = (bid & 63) >> 2;
    const int ks   = bid & 3;
    const int wn   = nt * 16 + wrp;          // col tile [wn*16, wn*16+16)
    const uint4* pbh = (const uint4*)g_wfh + ((size_t)(dirA * 256 + wn) * 64 + ks * 16) * 32 + lane;
    const uint4* pbl = (const uint4*)g_wfl + ((size_t)(dirA * 256 + wn) * 64 + ks * 16) * 32 + lane;
    const uint4* pah = (const uint4*)g_hfh + (size_t)(dirA * 64 + ks * 16) * 128 + lane;
    const uint4* pal = (const uint4*)g_hfl + (size_t)(dirA * 64 + ks * 16) * 128 + lane;

    // ---- phase B identifiers ----
    const int dirB = bid >> 6;
    const int cb   = bid & 63;
    const float* __restrict__ bhh  = dirB ? bhh_b  : bhh_f;
    const float* __restrict__ ghh  = dirB ? ghh_b  : ghh_f;
    const float* __restrict__ behh = dirB ? behh_b : behh_f;
    float* cptr = g_c + ((size_t)dirB * Bz + cb) * Hz + tid * 2;
    float* o2   = out + (size_t)Bz * Tz * 2 * Hz + (size_t)cb * (2 * Hz) + dirB * Hz + tid * 2;
    // h-frag write target: k0 = tid*2 -> one full word in hi & lo images
    const int kstepB = tid >> 3;
    const int pkB = tid & 7;
    const int r16B = cb & 15;
    const int mtB = cb >> 4;
    const size_t hwordB = ((size_t)(dirB * 64 + kstepB) * 4 + mtB) * 128
                          + ((r16B & 7) * 4 + (pkB & 3)) * 4
                          + (pkB >= 4 ? 2 : 0) + (r16B >= 8 ? 1 : 0);

    gbar();   // init visible

    for (int t = 0; t < Tz; t++) {
        // ================= phase A: HMMA GEMM (16 ksteps) =================
        float acc[4][2][4];
#pragma unroll
        for (int m = 0; m < 4; m++)
#pragma unroll
            for (int n = 0; n < 2; n++)
#pragma unroll
                for (int j = 0; j < 4; j++) acc[m][n][j] = 0.f;

        uint4 cbh = pbh[0], cbl = pbl[0];
#pragma unroll 4
        for (int kk = 0; kk < 16; kk++) {
            // A loads (h images, small, L1-resident across warps)
            const uint4* ah4 = pah + (size_t)kk * 128;
            const uint4* al4 = pal + (size_t)kk * 128;
            uint4 ah0 = ah4[0],  ah1 = ah4[32],  ah2 = ah4[64],  ah3 = ah4[96];
            uint4 al0 = al4[0],  al1 = al4[32],  al2 = al4[64],  al3 = al4[96];
            // B depth-1 prefetch (the L2-heavy W stream)
            uint4 nbh = cbh, nbl = cbl;
            if (kk < 15) {
                nbh = pbh[(size_t)(kk + 1) * 32];
                nbl = pbl[(size_t)(kk + 1) * 32];
            }
            mma16816(acc[0][0], ah0, cbh.x, cbh.y);
            mma16816(acc[0][0], al0, cbh.x, cbh.y);
            mma16816(acc[0][0], ah0, cbl.x, cbl.y);
            mma16816(acc[0][1], ah0, cbh.z, cbh.w);
            mma16816(acc[0][1], al0, cbh.z, cbh.w);
            mma16816(acc[0][1], ah0, cbl.z, cbl.w);
            mma16816(acc[1][0], ah1, cbh.x, cbh.y);
            mma16816(acc[1][0], al1, cbh.x, cbh.y);
            mma16816(acc[1][0], ah1, cbl.x, cbl.y);
            mma16816(acc[1][1], ah1, cbh.z, cbh.w);
            mma16816(acc[1][1], al1, cbh.z, cbh.w);
            mma16816(acc[1][1], ah1, cbl.z, cbl.w);
            mma16816(acc[2][0], ah2, cbh.x, cbh.y);
            mma16816(acc[2][0], al2, cbh.x, cbh.y);
            mma16816(acc[2][0], ah2, cbl.x, cbl.y);
            mma16816(acc[2][1], ah2, cbh.z, cbh.w);
            mma16816(acc[2][1], al2, cbh.z, cbh.w);
            mma16816(acc[2][1], ah2, cbl.z, cbl.w);
            mma16816(acc[3][0], ah3, cbh.x, cbh.y);
            mma16816(acc[3][0], al3, cbh.x, cbh.y);
            mma16816(acc[3][0], ah3, cbl.x, cbl.y);
            mma16816(acc[3][1], ah3, cbh.z, cbh.w);
            mma16816(acc[3][1], al3, cbh.z, cbh.w);
            mma16816(acc[3][1], ah3, cbl.z, cbl.w);
            cbh = nbh; cbl = nbl;
        }

        // epilogue: write C fragments to g_part [ks][dir][b][col]
        {
            const int r0 = lane >> 2;
            const int cc = wn * 16 + (lane & 3) * 2;
            float* pb = g_part + (size_t)(ks * 2 + dirA) * Bz * Gz;
#pragma unroll
            for (int m = 0; m < 4; m++) {
#pragma unroll
                for (int n = 0; n < 2; n++) {
                    int col = cc + n * 8;
                    *(float2*)&pb[(size_t)(m * 16 + r0) * Gz + col] =
                        make_float2(acc[m][n][0], acc[m][n][1]);
                    *(float2*)&pb[(size_t)(m * 16 + r0 + 8) * Gz + col] =
                        make_float2(acc[m][n][2], acc[m][n][3]);
                }
            }
        }

        gbar();   // all partial tiles visible

        // ================= phase B: sum 4 partials + LN + cell =================
        {
            float2 raw[4];
            float sum = 0.f, sq = 0.f;
#pragma unroll
            for (int g = 0; g < 4; g++) {
                int c = g * 1024 + tid * 2;
                const float* pbase = g_part + ((size_t)dirB * Bz + cb) * Gz + c;
                float2 p0 = *(const float2*)(pbase + (size_t)0 * 2 * Bz * Gz);
                float2 p1 = *(const float2*)(pbase + (size_t)1 * 2 * Bz * Gz);
                float2 p2 = *(const float2*)(pbase + (size_t)2 * 2 * Bz * Gz);
                float2 p3 = *(const float2*)(pbase + (size_t)3 * 2 * Bz * Gz);
                float2 bh = *(const float2*)(bhh + c);
                float2 r;
                r.x = p0.x + p1.x + p2.x + p3.x + bh.x;
                r.y = p0.y + p1.y + p2.y + p3.y + bh.y;
                raw[g] = r;
                sum += r.x + r.y;
                sq  += r.x * r.x + r.y * r.y;
            }
            red[tid] = sum; red[512 + tid] = sq;
            __syncthreads();
            for (int s = 256; s > 0; s >>= 1) {
                if (tid < s) { red[tid] += red[tid + s]; red[512 + tid] += red[512 + tid + s]; }
                __syncthreads();
            }
            float mu = red[0] * (1.f / Gz);
            float var = red[512] * (1.f / Gz) - mu * mu;
            float sc = rsqrtf(var + EPSz);

            const float* gih = g_gih + ((size_t)dirB * Tz * Bz + (size_t)t * Bz + cb) * Gz;
            float gate[4][2];
#pragma unroll
            for (int g = 0; g < 4; g++) {
                int c = g * 1024 + tid * 2;
                float2 gi = *(const float2*)(gih + c);
                float2 gg = *(const float2*)(ghh + c);
                float2 be = *(const float2*)(behh + c);
                gate[g][0] = gi.x + (raw[g].x - mu) * sc * gg.x + be.x;
                gate[g][1] = gi.y + (raw[g].y - mu) * sc * gg.y + be.y;
            }
            float* optr = out + ((size_t)cb * Tz + t) * (2 * Hz) + dirB * Hz + tid * 2;
            float hn2[2];
#pragma unroll
            for (int q = 0; q < 2; q++) {
                float iv = 1.f / (1.f + expf(-gate[0][q]));
                float fv = 1.f / (1.f + expf(-gate[1][q]));
                float gv = tanhf(gate[2][q]);
                float ov = 1.f / (1.f + expf(-gate[3][q]));
                float cn = fv * cptr[q] + iv * gv;
                float hn = ov * tanhf(cn);
                cptr[q] = cn;
                hn2[q] = hn;
                optr[q] = hn;
                if (t == Tz - 1) o2[q] = hn;
            }
            __nv_bfloat16 h0, l0, h1, l1;
            split_bf16(hn2[0], h0, l0);
            split_bf16(hn2[1], h1, l1);
            g_hfh[hwordB] = pack2(h0, h1);
            g_hfl[hwordB] = pack2(l0, l1);
        }

        gbar();   // new h visible
    }
}

// ---------------- launch ----------------
extern "C" void kernel_launch(void* const* d_in, const int* in_sizes, int n_in,
                              void* d_out, int out_size) {
    const float* x      = (const float*)d_in[0];
    const float* wih_f  = (const float*)d_in[1];
    const float* whh_f  = (const float*)d_in[2];
    const float* bih_f  = (const float*)d_in[3];
    const float* bhh_f  = (const float*)d_in[4];
    const float* gih_f  = (const float*)d_in[5];
    const float* beih_f = (const float*)d_in[6];
    const float* ghh_f  = (const float*)d_in[7];
    const float* behh_f = (const float*)d_in[8];
    const float* wih_b  = (const float*)d_in[9];
    const float* whh_b  = (const float*)d_in[10];
    const float* bih_b  = (const float*)d_in[11];
    const float* bhh_b  = (const float*)d_in[12];
    const float* gih_b  = (const float*)d_in[13];
    const float* beih_b = (const float*)d_in[14];
    const float* ghh_b  = (const float*)d_in[15];
    const float* behh_b = (const float*)d_in[16];
    const float* fwd_init = (const float*)d_in[17];
    const float* bwd_init = (const float*)d_in[18];
    float* out = (float*)d_out;

    prep_wfrag_kernel<<<4096, 256>>>(whh_f, whh_b, 0);
    prep_wfrag_kernel<<<4096, 256>>>(wih_f, wih_b, 1);
    prep_x_kernel<<<65536, 256>>>(x);
    gemm_ih_hmma<<<dim3(64, 256), 256>>>(bih_f, bih_b);
    ln_ih_kernel<<<65536, 256>>>(gih_f, beih_f, gih_b, beih_b);
    lstm_persistent<<<NCTA, 512>>>(bhh_f, ghh_f, behh_f,
                                   bhh_b, ghh_b, behh_b,
                                   fwd_init, bwd_init, out);
}

// round 10
// speedup vs baseline: 4.1446x; 1.0548x over previous
#include <cuda_runtime.h>
#include <cuda_bf16.h>
#include <math.h>
#include <stdint.h>

#define Bz 64
#define Tz 512
#define Dz 1024
#define Hz 1024
#define Gz 4096          // 4*H
#define EPSz 1e-5f
#define NCTA 128

typedef unsigned long long ull;

// ---------------- scratch (device globals; no runtime allocation) ----------------
__device__ float g_gih[(size_t)2 * Tz * Bz * Gz];      // LN'd input gates [dir][t][b][4H]
// W_hh fragment images: [dir][wn 0..255][kstep 0..63][128 words]
__device__ __align__(16) unsigned g_wfh[(size_t)2 * 256 * 64 * 128];
__device__ __align__(16) unsigned g_wfl[(size_t)2 * 256 * 64 * 128];
// W_ih fragment images (same shape: [4096][1024])
__device__ __align__(16) unsigned g_wihfh[(size_t)2 * 256 * 64 * 128];
__device__ __align__(16) unsigned g_wihfl[(size_t)2 * 256 * 64 * 128];
// x A-fragment images: [t 0..511][kstep 0..63][mt 0..3][128 words]
__device__ __align__(16) unsigned g_xfh[(size_t)512 * 64 * 4 * 128];
__device__ __align__(16) unsigned g_xfl[(size_t)512 * 64 * 4 * 128];
// h A-fragment images: [dir][kstep 0..63][mt 0..3][128 words]
__device__ __align__(16) unsigned g_hfh[2 * 64 * 4 * 128];
__device__ __align__(16) unsigned g_hfl[2 * 64 * 4 * 128];
__device__ float g_part[8 * Bz * Gz];                  // [ks 0..3][dir][b][4H]
__device__ float g_c[2 * Bz * Hz];                     // cell state
__device__ unsigned g_cnt = 0;
__device__ unsigned g_gen = 0;

// ---------------- helpers ----------------
__device__ __forceinline__ void split_bf16(float v, __nv_bfloat16& hi, __nv_bfloat16& lo) {
    hi = __float2bfloat16(v);
    lo = __float2bfloat16(v - __bfloat162float(hi));
}
__device__ __forceinline__ unsigned pack2(__nv_bfloat16 a, __nv_bfloat16 b) {
    return (unsigned)__bfloat16_as_ushort(a) | ((unsigned)__bfloat16_as_ushort(b) << 16);
}
__device__ __forceinline__ float tanh_ap(float x) {
    float y;
    asm("tanh.approx.f32 %0, %1;" : "=f"(y) : "f"(x));
    return y;
}
__device__ __forceinline__ float sig_ap(float x) {
    return 0.5f * tanh_ap(0.5f * x) + 0.5f;
}

// HMMA m16n8k16 bf16 row.col, f32 accumulate
__device__ __forceinline__ void mma16816(float* c, const uint4& a, unsigned b0, unsigned b1) {
    asm volatile(
        "mma.sync.aligned.m16n8k16.row.col.f32.bf16.bf16.f32 "
        "{%0,%1,%2,%3}, {%4,%5,%6,%7}, {%8,%9}, {%0,%1,%2,%3};"
        : "+f"(c[0]), "+f"(c[1]), "+f"(c[2]), "+f"(c[3])
        : "r"(a.x), "r"(a.y), "r"(a.z), "r"(a.w), "r"(b0), "r"(b1));
}

// grid-wide barrier (sense-reversing), all NCTA CTAs co-resident
__device__ __forceinline__ void gbar() {
    __syncthreads();
    if (threadIdx.x == 0) {
        unsigned gen = *(volatile unsigned*)&g_gen;
        __threadfence();
        unsigned old = atomicAdd(&g_cnt, 1u);
        if (old == NCTA - 1) {
            atomicExch(&g_cnt, 0u);
            __threadfence();
            atomicAdd(&g_gen, 1u);
        } else {
            while (*(volatile unsigned*)&g_gen == gen) __nanosleep(32);
        }
        __threadfence();
    }
    __syncthreads();
}

// ---------------- prep: weight [4096][1024] -> bf16 hi/lo B-fragment images ----------------
__global__ void prep_wfrag_kernel(const float* __restrict__ w_f, const float* __restrict__ w_b,
                                  int sel) {
    unsigned* __restrict__ outh = sel ? g_wihfh : g_wfh;
    unsigned* __restrict__ outl = sel ? g_wihfl : g_wfl;
    int gid = blockIdx.x * 256 + threadIdx.x;
    int T     = gid & 31;
    int kstep = (gid >> 5) & 63;
    int wn    = (gid >> 11) & 255;
    int dir   = gid >> 19;
    const float* __restrict__ W = dir ? w_b : w_f;
    unsigned hw[4], lw[4];
#pragma unroll
    for (int q = 0; q < 4; q++) {
        int c = wn * 16 + (q >> 1) * 8 + (T >> 2);
        int k = kstep * 16 + ((q & 1) * 4 + (T & 3)) * 2;
        float2 v = *(const float2*)(W + (size_t)c * Hz + k);
        __nv_bfloat16 h0, l0, h1, l1;
        split_bf16(v.x, h0, l0);
        split_bf16(v.y, h1, l1);
        hw[q] = pack2(h0, h1);
        lw[q] = pack2(l0, l1);
    }
    size_t base = ((size_t)(dir * 256 + wn) * 64 + kstep) * 128 + T * 4;
    *(uint4*)&outh[base] = make_uint4(hw[0], hw[1], hw[2], hw[3]);
    *(uint4*)&outl[base] = make_uint4(lw[0], lw[1], lw[2], lw[3]);
}

// ---------------- prep: x -> bf16 hi/lo A-fragment images ----------------
__global__ void prep_x_kernel(const float* __restrict__ x) {
    int gid = blockIdx.x * 256 + threadIdx.x;
    int kw = gid & 511;
    int b  = (gid >> 9) & 63;
    int t  = gid >> 15;
    float2 v = *(const float2*)(x + ((size_t)b * Tz + t) * Dz + kw * 2);
    __nv_bfloat16 h0, l0, h1, l1;
    split_bf16(v.x, h0, l0);
    split_bf16(v.y, h1, l1);
    int kstep = kw >> 3;
    int pk = kw & 7;
    int r16 = b & 15;
    int mt = b >> 4;
    int T = (r16 & 7) * 4 + (pk & 3);
    int q = (pk >= 4 ? 2 : 0) + (r16 >= 8 ? 1 : 0);
    size_t widx = ((size_t)(t * 64 + kstep) * 4 + mt) * 128 + T * 4 + q;
    g_xfh[widx] = pack2(h0, h1);
    g_xfl[widx] = pack2(l0, l1);
}

// ---------------- input-side GEMM: HMMA bf16-split (unchanged) ----------------
__global__ __launch_bounds__(256)
void gemm_ih_hmma(const float* __restrict__ bias_f, const float* __restrict__ bias_b) {
    __shared__ uint4 As[2][512];
    __shared__ uint4 Al[2][512];
    const int tid = threadIdx.x;
    const int lane = tid & 31;
    const int wrp = tid >> 5;
    const int dir = blockIdx.x >> 5;
    const int ntile = blockIdx.x & 31;
    const int mtile = blockIdx.y;
    const int wm = wrp >> 2;
    const int wn4 = wrp & 3;
    const float* __restrict__ bias = dir ? bias_b : bias_f;

    const int wn0 = ntile * 8 + wn4 * 2;
    const uint4* pb0h = (const uint4*)g_wihfh + ((size_t)(dir * 256 + wn0) * 64) * 32 + lane;
    const uint4* pb0l = (const uint4*)g_wihfl + ((size_t)(dir * 256 + wn0) * 64) * 32 + lane;
    const uint4* pb1h = (const uint4*)g_wihfh + ((size_t)(dir * 256 + wn0 + 1) * 64) * 32 + lane;
    const uint4* pb1l = (const uint4*)g_wihfl + ((size_t)(dir * 256 + wn0 + 1) * 64) * 32 + lane;

    const uint4* gxh = (const uint4*)g_xfh;
    const uint4* gxl = (const uint4*)g_xfl;

    auto gaddrA = [&](int c, int u) -> size_t {
        int block = u >> 5;
        int ks2 = block >> 3;
        int mtg = block & 7;
        int l4 = u & 31;
        int v = mtile * 2 + (mtg >> 2);
        int t = dir ? (511 - v) : v;
        return ((size_t)(t * 64 + c * 2 + ks2) * 4 + (mtg & 3)) * 32 + l4;
    };

    float acc[4][4][4];
#pragma unroll
    for (int i = 0; i < 4; i++)
#pragma unroll
        for (int n = 0; n < 4; n++)
#pragma unroll
            for (int j = 0; j < 4; j++) acc[i][n][j] = 0.f;

    As[0][tid] = gxh[gaddrA(0, tid)];
    As[0][tid + 256] = gxh[gaddrA(0, tid + 256)];
    Al[0][tid] = gxl[gaddrA(0, tid)];
    Al[0][tid + 256] = gxl[gaddrA(0, tid + 256)];
    __syncthreads();

    uint4 cb0h = pb0h[0], cb0l = pb0l[0], cb1h = pb1h[0], cb1l = pb1l[0];

    for (int c = 0; c < 32; c++) {
        const int cur = c & 1;
        uint4 rh0, rh1, rl0, rl1;
        if (c < 31) {
            rh0 = gxh[gaddrA(c + 1, tid)];
            rh1 = gxh[gaddrA(c + 1, tid + 256)];
            rl0 = gxl[gaddrA(c + 1, tid)];
            rl1 = gxl[gaddrA(c + 1, tid + 256)];
        }
#pragma unroll
        for (int ks2 = 0; ks2 < 2; ks2++) {
            const int kstep = c * 2 + ks2;
            uint4 nb0h = cb0h, nb0l = cb0l, nb1h = cb1h, nb1l = cb1l;
            if (kstep < 63) {
                size_t o = (size_t)(kstep + 1) * 32;
                nb0h = pb0h[o]; nb0l = pb0l[o];
                nb1h = pb1h[o]; nb1l = pb1l[o];
            }
            uint4 ah[4], al[4];
#pragma unroll
            for (int i = 0; i < 4; i++) {
                int sb = (ks2 * 8 + wm * 4 + i) * 32 + lane;
                ah[i] = As[cur][sb];
                al[i] = Al[cur][sb];
            }
#pragma unroll
            for (int i = 0; i < 4; i++) {
                mma16816(acc[i][0], ah[i], cb0h.x, cb0h.y);
                mma16816(acc[i][0], al[i], cb0h.x, cb0h.y);
                mma16816(acc[i][0], ah[i], cb0l.x, cb0l.y);
                mma16816(acc[i][1], ah[i], cb0h.z, cb0h.w);
                mma16816(acc[i][1], al[i], cb0h.z, cb0h.w);
                mma16816(acc[i][1], ah[i], cb0l.z, cb0l.w);
                mma16816(acc[i][2], ah[i], cb1h.x, cb1h.y);
                mma16816(acc[i][2], al[i], cb1h.x, cb1h.y);
                mma16816(acc[i][2], ah[i], cb1l.x, cb1l.y);
                mma16816(acc[i][3], ah[i], cb1h.z, cb1h.w);
                mma16816(acc[i][3], al[i], cb1h.z, cb1h.w);
                mma16816(acc[i][3], ah[i], cb1l.z, cb1l.w);
            }
            cb0h = nb0h; cb0l = nb0l; cb1h = nb1h; cb1l = nb1l;
        }
        if (c < 31) {
            const int nxt = cur ^ 1;
            As[nxt][tid] = rh0; As[nxt][tid + 256] = rh1;
            Al[nxt][tid] = rl0; Al[nxt][tid + 256] = rl1;
            __syncthreads();
        }
    }

    const int r0 = lane >> 2;
    const int cp = (lane & 3) * 2;
    float* outbase = g_gih + (size_t)dir * (Tz * Bz) * Gz;
#pragma unroll
    for (int i = 0; i < 4; i++) {
        const int mtg = wm * 4 + i;
        const int rbase = mtile * 128 + (mtg >> 2) * 64 + (mtg & 3) * 16;
#pragma unroll
        for (int n8 = 0; n8 < 4; n8++) {
            const int col = ntile * 128 + wn4 * 32 + n8 * 8 + cp;
            float2 bv = *(const float2*)(bias + col);
            float* d0 = outbase + (size_t)(rbase + r0) * Gz + col;
            float* d1 = outbase + (size_t)(rbase + r0 + 8) * Gz + col;
            *(float2*)d0 = make_float2(acc[i][n8][0] + bv.x, acc[i][n8][1] + bv.y);
            *(float2*)d1 = make_float2(acc[i][n8][2] + bv.x, acc[i][n8][3] + bv.y);
        }
    }
}

// ---------------- LayerNorm over 4096 (in place) ----------------
__global__ void ln_ih_kernel(const float* __restrict__ gain_f, const float* __restrict__ beta_f,
                             const float* __restrict__ gain_b, const float* __restrict__ beta_b) {
    const int row = blockIdx.x;
    const int dir = row >> 15;
    const float* __restrict__ gain = dir ? gain_b : gain_f;
    const float* __restrict__ beta = dir ? beta_b : beta_f;
    float* p = g_gih + (size_t)row * Gz;
    const int tid = threadIdx.x;

    float4 v[4];
    float sum = 0.f, sq = 0.f;
#pragma unroll
    for (int g = 0; g < 4; g++) {
        v[g] = *(const float4*)(p + g * 1024 + tid * 4);
        sum += v[g].x + v[g].y + v[g].z + v[g].w;
        sq  += v[g].x * v[g].x + v[g].y * v[g].y + v[g].z * v[g].z + v[g].w * v[g].w;
    }
    __shared__ float red[512];
    red[tid] = sum; red[256 + tid] = sq;
    __syncthreads();
    for (int s = 128; s > 0; s >>= 1) {
        if (tid < s) { red[tid] += red[tid + s]; red[256 + tid] += red[256 + tid + s]; }
        __syncthreads();
    }
    float mu = red[0] * (1.f / Gz);
    float var = red[256] * (1.f / Gz) - mu * mu;
    float sc = rsqrtf(var + EPSz);
#pragma unroll
    for (int g = 0; g < 4; g++) {
        int c = g * 1024 + tid * 4;
        float4 gv = *(const float4*)(gain + c);
        float4 bvv = *(const float4*)(beta + c);
        float4 o;
        o.x = (v[g].x - mu) * sc * gv.x + bvv.x;
        o.y = (v[g].y - mu) * sc * gv.y + bvv.y;
        o.z = (v[g].z - mu) * sc * gv.z + bvv.z;
        o.w = (v[g].w - mu) * sc * gv.w + bvv.w;
        *(float4*)(p + c) = o;
    }
}

// h A-fragment write: element (b=row, k) of dir -> word index
__device__ __forceinline__ void hfrag_addr(int dir, int b, int k, size_t& widx) {
    int kstep = k >> 4;
    int pk = (k >> 1) & 7;
    int r16 = b & 15;
    int mt = b >> 4;
    int T = (r16 & 7) * 4 + (pk & 3);
    int q = (pk >= 4 ? 2 : 0) + (r16 >= 8 ? 1 : 0);
    widx = ((size_t)(dir * 64 + kstep) * 4 + mt) * 128 + T * 4 + q;
}

// ---------------- persistent recurrence: W-hi SMEM-resident, short serial chain ----------------
// SMEM: ws[8192 uint4] = per-CTA W-hi slice (16 wn x 16 ksteps), loaded once. red[64].
#define SMEM_BYTES (131072 + 256)

__global__ __launch_bounds__(512, 1)
void lstm_persistent(const float* __restrict__ bhh_f, const float* __restrict__ ghh_f,
                     const float* __restrict__ behh_f,
                     const float* __restrict__ bhh_b, const float* __restrict__ ghh_b,
                     const float* __restrict__ behh_b,
                     const float* __restrict__ fwd_init, const float* __restrict__ bwd_init,
                     float* __restrict__ out) {
    extern __shared__ __align__(16) char smem[];
    uint4* ws = (uint4*)smem;                       // [16 wn][16 kstep][32 uint4]
    float* red = (float*)(smem + 131072);           // [64]

    const int tid = threadIdx.x;
    const int bid = blockIdx.x;
    const int wrp = tid >> 5;
    const int lane = tid & 31;

    // ---- init h0/c0 ----
    for (int i = bid * 512 + tid; i < 2 * Bz * Hz; i += NCTA * 512) {
        int dir0 = i >> 16;
        int b = (i >> 10) & 63;
        int k = i & 1023;
        const float* init = dir0 ? bwd_init : fwd_init;
        float hv = init[k];
        g_c[(size_t)(dir0 * Bz + b) * Hz + k] = init[Hz + k];
        __nv_bfloat16 hh, hl;
        split_bf16(hv, hh, hl);
        size_t widx;
        hfrag_addr(dir0, b, k, widx);
        int half = k & 1;
        ((__nv_bfloat16*)&g_hfh[widx])[half] = hh;
        ((__nv_bfloat16*)&g_hfl[widx])[half] = hl;
    }

    // ---- phase A identifiers: bid = dir*64 + nt*4 + ks ----
    const int dirA = bid >> 6;
    const int nt   = (bid & 63) >> 2;
    const int ks   = bid & 3;
    const int wn   = nt * 16 + wrp;
    const uint4* pbl = (const uint4*)g_wfl + ((size_t)(dirA * 256 + wn) * 64 + ks * 16) * 32 + lane;
    const uint4* pah = (const uint4*)g_hfh + (size_t)(dirA * 64 + ks * 16) * 128 + lane;
    const uint4* pal = (const uint4*)g_hfl + (size_t)(dirA * 64 + ks * 16) * 128 + lane;

    // ---- load per-CTA W-hi slice into SMEM (once) ----
    {
        const uint4* src = (const uint4*)g_wfh
            + ((size_t)(dirA * 256 + nt * 16) * 64 + ks * 16) * 32;
        // src layout over w: stride between wn's = 64*32 uint4; we need [w][16k][32]
#pragma unroll
        for (int j = 0; j < 16; j++) {
            int u = tid + j * 512;          // 0..8191
            int w = u >> 9;
            int rem = u & 511;              // k*32 + l4
            ws[u] = src[(size_t)w * (64 * 32) + rem];
        }
    }

    // ---- phase B identifiers ----
    const int dirB = bid >> 6;
    const int cb   = bid & 63;
    const float* __restrict__ bhh  = dirB ? bhh_b  : bhh_f;
    const float* __restrict__ ghh  = dirB ? ghh_b  : ghh_f;
    const float* __restrict__ behh = dirB ? behh_b : behh_f;
    float* cptr = g_c + ((size_t)dirB * Bz + cb) * Hz + tid * 2;
    float* o2   = out + (size_t)Bz * Tz * 2 * Hz + (size_t)cb * (2 * Hz) + dirB * Hz + tid * 2;
    const int kstepB = tid >> 3;
    const int pkB = tid & 7;
    const int r16B = cb & 15;
    const int mtB = cb >> 4;
    const size_t hwordB = ((size_t)(dirB * 64 + kstepB) * 4 + mtB) * 128
                          + ((r16B & 7) * 4 + (pkB & 3)) * 4
                          + (pkB >= 4 ? 2 : 0) + (r16B >= 8 ? 1 : 0);

    gbar();   // init + SMEM W visible/loaded

    for (int t = 0; t < Tz; t++) {
        // ---- prefetch this step's gih slice (independent of barriers) ----
        float2 gi[4];
        {
            const float* gih = g_gih + ((size_t)dirB * Tz * Bz + (size_t)t * Bz + cb) * Gz;
#pragma unroll
            for (int g = 0; g < 4; g++)
                gi[g] = *(const float2*)(gih + g * 1024 + tid * 2);
        }

        // ================= phase A: HMMA GEMM (16 ksteps, B-hi from SMEM) =================
        float acc[4][2][4];
#pragma unroll
        for (int m = 0; m < 4; m++)
#pragma unroll
            for (int n = 0; n < 2; n++)
#pragma unroll
                for (int j = 0; j < 4; j++) acc[m][n][j] = 0.f;

        uint4 cbl = pbl[0];
#pragma unroll 4
        for (int kk = 0; kk < 16; kk++) {
            const uint4* ah4 = pah + (size_t)kk * 128;
            const uint4* al4 = pal + (size_t)kk * 128;
            uint4 ah0 = ah4[0],  ah1 = ah4[32],  ah2 = ah4[64],  ah3 = ah4[96];
            uint4 al0 = al4[0],  al1 = al4[32],  al2 = al4[64],  al3 = al4[96];
            uint4 cbh = ws[(wrp * 16 + kk) * 32 + lane];
            uint4 nbl = cbl;
            if (kk < 15) nbl = pbl[(size_t)(kk + 1) * 32];
            mma16816(acc[0][0], ah0, cbh.x, cbh.y);
            mma16816(acc[0][0], al0, cbh.x, cbh.y);
            mma16816(acc[0][0], ah0, cbl.x, cbl.y);
            mma16816(acc[0][1], ah0, cbh.z, cbh.w);
            mma16816(acc[0][1], al0, cbh.z, cbh.w);
            mma16816(acc[0][1], ah0, cbl.z, cbl.w);
            mma16816(acc[1][0], ah1, cbh.x, cbh.y);
            mma16816(acc[1][0], al1, cbh.x, cbh.y);
            mma16816(acc[1][0], ah1, cbl.x, cbl.y);
            mma16816(acc[1][1], ah1, cbh.z, cbh.w);
            mma16816(acc[1][1], al1, cbh.z, cbh.w);
            mma16816(acc[1][1], ah1, cbl.z, cbl.w);
            mma16816(acc[2][0], ah2, cbh.x, cbh.y);
            mma16816(acc[2][0], al2, cbh.x, cbh.y);
            mma16816(acc[2][0], ah2, cbl.x, cbl.y);
            mma16816(acc[2][1], ah2, cbh.z, cbh.w);
            mma16816(acc[2][1], al2, cbh.z, cbh.w);
            mma16816(acc[2][1], ah2, cbl.z, cbl.w);
            mma16816(acc[3][0], ah3, cbh.x, cbh.y);
            mma16816(acc[3][0], al3, cbh.x, cbh.y);
            mma16816(acc[3][0], ah3, cbl.x, cbl.y);
            mma16816(acc[3][1], ah3, cbh.z, cbh.w);
            mma16816(acc[3][1], al3, cbh.z, cbh.w);
            mma16816(acc[3][1], ah3, cbl.z, cbl.w);
            cbl = nbl;
        }

        // epilogue: write C fragments to g_part [ks][dir][b][col]
        {
            const int r0 = lane >> 2;
            const int cc = wn * 16 + (lane & 3) * 2;
            float* pb = g_part + (size_t)(ks * 2 + dirA) * Bz * Gz;
#pragma unroll
            for (int m = 0; m < 4; m++) {
#pragma unroll
                for (int n = 0; n < 2; n++) {
                    int col = cc + n * 8;
                    *(float2*)&pb[(size_t)(m * 16 + r0) * Gz + col] =
                        make_float2(acc[m][n][0], acc[m][n][1]);
                    *(float2*)&pb[(size_t)(m * 16 + r0 + 8) * Gz + col] =
                        make_float2(acc[m][n][2], acc[m][n][3]);
                }
            }
        }

        gbar();   // all partial tiles visible

        // ================= phase B: sum 4 partials + LN + cell =================
        {
            float2 raw[4];
            float sum = 0.f, sq = 0.f;
#pragma unroll
            for (int g = 0; g < 4; g++) {
                int c = g * 1024 + tid * 2;
                const float* pbase = g_part + ((size_t)dirB * Bz + cb) * Gz + c;
                float2 p0 = *(const float2*)(pbase + (size_t)0 * 2 * Bz * Gz);
                float2 p1 = *(const float2*)(pbase + (size_t)1 * 2 * Bz * Gz);
                float2 p2 = *(const float2*)(pbase + (size_t)2 * 2 * Bz * Gz);
                float2 p3 = *(const float2*)(pbase + (size_t)3 * 2 * Bz * Gz);
                float2 bh = *(const float2*)(bhh + c);
                float2 r;
                r.x = p0.x + p1.x + p2.x + p3.x + bh.x;
                r.y = p0.y + p1.y + p2.y + p3.y + bh.y;
                raw[g] = r;
                sum += r.x + r.y;
                sq  += r.x * r.x + r.y * r.y;
            }
            // warp shfl reduction + single cross-warp stage
#pragma unroll
            for (int off = 16; off; off >>= 1) {
                sum += __shfl_xor_sync(0xffffffffu, sum, off);
                sq  += __shfl_xor_sync(0xffffffffu, sq, off);
            }
            if (lane == 0) { red[wrp] = sum; red[32 + wrp] = sq; }
            __syncthreads();
            float ts = 0.f, tq = 0.f;
#pragma unroll
            for (int i = 0; i < 16; i++) { ts += red[i]; tq += red[32 + i]; }
            float mu = ts * (1.f / Gz);
            float var = tq * (1.f / Gz) - mu * mu;
            float sc = rsqrtf(var + EPSz);

            float gate[4][2];
#pragma unroll
            for (int g = 0; g < 4; g++) {
                int c = g * 1024 + tid * 2;
                float2 gg = *(const float2*)(ghh + c);
                float2 be = *(const float2*)(behh + c);
                gate[g][0] = gi[g].x + (raw[g].x - mu) * sc * gg.x + be.x;
                gate[g][1] = gi[g].y + (raw[g].y - mu) * sc * gg.y + be.y;
            }
            float* optr = out + ((size_t)cb * Tz + t) * (2 * Hz) + dirB * Hz + tid * 2;
            float hn2[2];
#pragma unroll
            for (int q = 0; q < 2; q++) {
                float iv = sig_ap(gate[0][q]);
                float fv = sig_ap(gate[1][q]);
                float gv = tanh_ap(gate[2][q]);
                float ov = sig_ap(gate[3][q]);
                float cn = fv * cptr[q] + iv * gv;
                float hn = ov * tanh_ap(cn);
                cptr[q] = cn;
                hn2[q] = hn;
                optr[q] = hn;
                if (t == Tz - 1) o2[q] = hn;
            }
            __nv_bfloat16 h0, l0, h1, l1;
            split_bf16(hn2[0], h0, l0);
            split_bf16(hn2[1], h1, l1);
            g_hfh[hwordB] = pack2(h0, h1);
            g_hfl[hwordB] = pack2(l0, l1);
        }

        gbar();   // new h visible
    }
}

// ---------------- launch ----------------
extern "C" void kernel_launch(void* const* d_in, const int* in_sizes, int n_in,
                              void* d_out, int out_size) {
    const float* x      = (const float*)d_in[0];
    const float* wih_f  = (const float*)d_in[1];
    const float* whh_f  = (const float*)d_in[2];
    const float* bih_f  = (const float*)d_in[3];
    const float* bhh_f  = (const float*)d_in[4];
    const float* gih_f  = (const float*)d_in[5];
    const float* beih_f = (const float*)d_in[6];
    const float* ghh_f  = (const float*)d_in[7];
    const float* behh_f = (const float*)d_in[8];
    const float* wih_b  = (const float*)d_in[9];
    const float* whh_b  = (const float*)d_in[10];
    const float* bih_b  = (const float*)d_in[11];
    const float* bhh_b  = (const float*)d_in[12];
    const float* gih_b  = (const float*)d_in[13];
    const float* beih_b = (const float*)d_in[14];
    const float* ghh_b  = (const float*)d_in[15];
    const float* behh_b = (const float*)d_in[16];
    const float* fwd_init = (const float*)d_in[17];
    const float* bwd_init = (const float*)d_in[18];
    float* out = (float*)d_out;

    static int smem_set = 0;
    if (!smem_set) {
        cudaFuncSetAttribute(lstm_persistent,
                             cudaFuncAttributeMaxDynamicSharedMemorySize, SMEM_BYTES);
        smem_set = 1;
    }

    prep_wfrag_kernel<<<4096, 256>>>(whh_f, whh_b, 0);
    prep_wfrag_kernel<<<4096, 256>>>(wih_f, wih_b, 1);
    prep_x_kernel<<<65536, 256>>>(x);
    gemm_ih_hmma<<<dim3(64, 256), 256>>>(bih_f, bih_b);
    ln_ih_kernel<<<65536, 256>>>(gih_f, beih_f, gih_b, beih_b);
    lstm_persistent<<<NCTA, 512, SMEM_BYTES>>>(bhh_f, ghh_f, behh_f,
                                               bhh_b, ghh_b, behh_b,
                                               fwd_init, bwd_init, out);
}